// round 13
// baseline (speedup 1.0000x reference)
#include <cuda_runtime.h>
#include <cuda_bf16.h>
#include <cstdint>
#include <math.h>

#define NN 16384
#define HH 8
#define DD 64
#define LL 65
#define BHH 16
#define NSPLIT 16
#define CHUNK 1024
#define DIMM 512
#define QKVN 1536

// ------------------ device scratch (allocation-free rule) -------------------
__device__ float g_q[(size_t)BHH * NN * DD];
__device__ float g_k[(size_t)BHH * NN * DD];
__device__ float g_v[(size_t)BHH * NN * DD];
__device__ float g_ql[BHH * LL * DD];
__device__ float g_kl[BHH * LL * DD];
__device__ float g_attn2[BHH * LL * LL];
__device__ float g_z[BHH * LL * LL];
__device__ float g_scal[1];
__device__ float g_pm[BHH * NSPLIT * LL];
__device__ float g_pl[BHH * NSPLIT * LL];
__device__ float g_pacc[BHH * NSPLIT * LL * DD];
__device__ float g_tmp1[BHH * LL * DD];
__device__ float g_tmp2[BHH * LL * DD];
__device__ int   g_segcnt[LL];
__device__ int   g_segoff[LL + 1];
// bf16 hi/lo staging
__device__ __nv_bfloat16 g_xqh[(size_t)2 * NN * DIMM];
__device__ __nv_bfloat16 g_xql[(size_t)2 * NN * DIMM];
__device__ __nv_bfloat16 g_wqh[DIMM * QKVN];
__device__ __nv_bfloat16 g_wql[DIMM * QKVN];
__device__ __nv_bfloat16 g_oh[(size_t)2 * NN * DIMM];
__device__ __nv_bfloat16 g_ol[(size_t)2 * NN * DIMM];
__device__ __nv_bfloat16 g_woh[DIMM * DIMM];
__device__ __nv_bfloat16 g_wol[DIMM * DIMM];

// ================== mma.sync helpers =========
__device__ __forceinline__ void mma16816(float* c, const uint32_t* a, const uint32_t* b) {
    asm volatile(
        "mma.sync.aligned.m16n8k16.row.col.f32.bf16.bf16.f32 "
        "{%0,%1,%2,%3}, {%4,%5,%6,%7}, {%8,%9}, {%0,%1,%2,%3};"
        : "+f"(c[0]), "+f"(c[1]), "+f"(c[2]), "+f"(c[3])
        : "r"(a[0]), "r"(a[1]), "r"(a[2]), "r"(a[3]), "r"(b[0]), "r"(b[1]));
}
__device__ __forceinline__ void ldmx4(uint32_t* r, uint32_t addr) {
    asm volatile("ldmatrix.sync.aligned.m8n8.x4.shared.b16 {%0,%1,%2,%3}, [%4];"
                 : "=r"(r[0]), "=r"(r[1]), "=r"(r[2]), "=r"(r[3]) : "r"(addr));
}
__device__ __forceinline__ void ldmx2t(uint32_t* r, uint32_t addr) {
    asm volatile("ldmatrix.sync.aligned.m8n8.x2.trans.shared.b16 {%0,%1}, [%2];"
                 : "=r"(r[0]), "=r"(r[1]) : "r"(addr));
}
__device__ __forceinline__ void bf_split(float v, __nv_bfloat16& h, __nv_bfloat16& l) {
    h = __float2bfloat16(v);
    l = __float2bfloat16(v - __bfloat162float(h));
}
__device__ __forceinline__ uint32_t pack2(__nv_bfloat16 a, __nv_bfloat16 b) {
    return (uint32_t)__bfloat16_as_ushort(a) | ((uint32_t)__bfloat16_as_ushort(b) << 16);
}

#define BP 40   // A smem row pitch (bf16 elems)
#define BPB 72  // B smem row pitch (bf16 elems), k-major 32x72

// ------------------ segment offsets ------------------
__global__ void seg_init_kernel() { if (threadIdx.x < LL) g_segcnt[threadIdx.x] = 0; }
__global__ void seg_count_kernel(const int* __restrict__ seg) {
    int i = blockIdx.x * 256 + threadIdx.x;
    if (i < NN) atomicAdd(&g_segcnt[seg[i]], 1);
}
__global__ void seg_scan_kernel() {
    if (threadIdx.x == 0) {
        int acc = 0;
        for (int j = 0; j < LL; j++) { g_segoff[j] = acc; acc += g_segcnt[j]; }
        g_segoff[LL] = acc;
    }
}

// ------------------ conversion kernels (union-free) ------------------
__global__ __launch_bounds__(256) void conv_x_kernel(
    const float* __restrict__ x, const int* __restrict__ index) {
    size_t idx = ((size_t)blockIdx.x * 256 + threadIdx.x) * 8;
    int r = (int)(idx >> 9), c = (int)(idx & 511);
    int b = r >> 14, i = r & (NN - 1);
    int ar = b * NN + index[i];
    const float* s = x + (size_t)ar * DIMM + c;
    float4 v0 = *(const float4*)s, v1 = *(const float4*)(s + 4);
    __nv_bfloat16 h0, h1, h2, h3, h4, h5, h6, h7;
    __nv_bfloat16 l0, l1, l2, l3, l4, l5, l6, l7;
    bf_split(v0.x, h0, l0); bf_split(v0.y, h1, l1);
    bf_split(v0.z, h2, l2); bf_split(v0.w, h3, l3);
    bf_split(v1.x, h4, l4); bf_split(v1.y, h5, l5);
    bf_split(v1.z, h6, l6); bf_split(v1.w, h7, l7);
    uint4 H = make_uint4(pack2(h0, h1), pack2(h2, h3), pack2(h4, h5), pack2(h6, h7));
    uint4 L = make_uint4(pack2(l0, l1), pack2(l2, l3), pack2(l4, l5), pack2(l6, l7));
    *(uint4*)(g_xqh + idx) = H;
    *(uint4*)(g_xql + idx) = L;
}
__global__ __launch_bounds__(256) void conv_w_kernel(
    const float* __restrict__ src, __nv_bfloat16* __restrict__ dh,
    __nv_bfloat16* __restrict__ dl) {
    size_t idx = ((size_t)blockIdx.x * 256 + threadIdx.x) * 8;
    float4 v0 = *(const float4*)(src + idx), v1 = *(const float4*)(src + idx + 4);
    __nv_bfloat16 h0, h1, h2, h3, h4, h5, h6, h7;
    __nv_bfloat16 l0, l1, l2, l3, l4, l5, l6, l7;
    bf_split(v0.x, h0, l0); bf_split(v0.y, h1, l1);
    bf_split(v0.z, h2, l2); bf_split(v0.w, h3, l3);
    bf_split(v1.x, h4, l4); bf_split(v1.y, h5, l5);
    bf_split(v1.z, h6, l6); bf_split(v1.w, h7, l7);
    uint4 H = make_uint4(pack2(h0, h1), pack2(h2, h3), pack2(h4, h5), pack2(h6, h7));
    uint4 L = make_uint4(pack2(l0, l1), pack2(l2, l3), pack2(l4, l5), pack2(l6, l7));
    *(uint4*)(dh + idx) = H;
    *(uint4*)(dl + idx) = L;
}

// ========== QKV GEMM: 128x64 tile (2 CTAs/SM target), bf16 hi/lo ============
__global__ __launch_bounds__(256, 1) void qkv_mma_kernel() {
    __shared__ __nv_bfloat16 sAh[128][BP], sAl[128][BP];
    __shared__ __nv_bfloat16 sBh[32][BPB], sBl[32][BPB];
    const int tid = threadIdx.x, lane = tid & 31, wid = tid >> 5;
    const int wm = wid & 1, wn = wid >> 1;   // 2 x 4: warp tile 64x16
    const int cb = blockIdx.x * 64, row0 = blockIdx.y * 128;

    const int ar = tid >> 1, akb = (tid & 1) << 4;
    const int bkr = tid & 31, bnf = (tid >> 5) << 3;   // 8 warps x 8 cols
    const __nv_bfloat16* gah = g_xqh + (size_t)(row0 + ar) * DIMM + akb;
    const __nv_bfloat16* gal = g_xql + (size_t)(row0 + ar) * DIMM + akb;
    const __nv_bfloat16* gbh = g_wqh + (size_t)bkr * QKVN + cb + bnf;
    const __nv_bfloat16* gbl = g_wql + (size_t)bkr * QKVN + cb + bnf;

    float acc[4][2][4] = {};

    uint4 rah  = *(const uint4*)(gah);
    uint4 rah2 = *(const uint4*)(gah + 8);
    uint4 ral  = *(const uint4*)(gal);
    uint4 ral2 = *(const uint4*)(gal + 8);
    uint4 rbh  = *(const uint4*)(gbh);
    uint4 rbl  = *(const uint4*)(gbl);

    for (int c = 0; c < 16; c++) {
        *(uint4*)&sAh[ar][akb]     = rah;
        *(uint4*)&sAh[ar][akb + 8] = rah2;
        *(uint4*)&sAl[ar][akb]     = ral;
        *(uint4*)&sAl[ar][akb + 8] = ral2;
        *(uint4*)&sBh[bkr][bnf] = rbh;
        *(uint4*)&sBl[bkr][bnf] = rbl;
        __syncthreads();
        if (c + 1 < 16) {
            const int k0 = (c + 1) * 32;
            rah  = *(const uint4*)(gah + k0);
            rah2 = *(const uint4*)(gah + k0 + 8);
            ral  = *(const uint4*)(gal + k0);
            ral2 = *(const uint4*)(gal + k0 + 8);
            rbh  = *(const uint4*)(gbh + (size_t)k0 * QKVN);
            rbl  = *(const uint4*)(gbl + (size_t)k0 * QKVN);
        }
#pragma unroll
        for (int ks = 0; ks < 2; ks++) {
            uint32_t ah[4][4], al[4][4], bh[2][2], bl[2][2];
            const int acol = ks * 16 + ((lane >> 4) << 3);
            const int krow = ks * 16 + (lane & 15);
#pragma unroll
            for (int mt = 0; mt < 4; mt++) {
                int arw = wm * 64 + mt * 16 + (lane & 15);
                ldmx4(ah[mt], (uint32_t)__cvta_generic_to_shared(&sAh[arw][acol]));
                ldmx4(al[mt], (uint32_t)__cvta_generic_to_shared(&sAl[arw][acol]));
            }
#pragma unroll
            for (int nt = 0; nt < 2; nt++) {
                int n0 = wn * 16 + nt * 8;
                ldmx2t(bh[nt], (uint32_t)__cvta_generic_to_shared(&sBh[krow][n0]));
                ldmx2t(bl[nt], (uint32_t)__cvta_generic_to_shared(&sBl[krow][n0]));
            }
#pragma unroll
            for (int mt = 0; mt < 4; mt++)
#pragma unroll
                for (int nt = 0; nt < 2; nt++) {
                    mma16816(acc[mt][nt], ah[mt], bh[nt]);
                    mma16816(acc[mt][nt], ah[mt], bl[nt]);
                    mma16816(acc[mt][nt], al[mt], bh[nt]);
                }
        }
        __syncthreads();
    }

    const int part = cb >> 9;
    float* dst = part == 0 ? g_q : (part == 1 ? g_k : g_v);
    const float sc = part == 0 ? 0.125f : 1.f;
    const int hd = (cb >> 6) & 7;
#pragma unroll
    for (int mt = 0; mt < 4; mt++) {
#pragma unroll
        for (int nt = 0; nt < 2; nt++) {
            int d0 = wn * 16 + nt * 8 + (lane & 3) * 2;
#pragma unroll
            for (int half = 0; half < 2; half++) {
                int r = row0 + wm * 64 + mt * 16 + (lane >> 2) + half * 8;
                int b = r >> 14, i = r & (NN - 1);
                float* p = dst + ((size_t)(b * HH + hd) * NN + i) * DD + d0;
                *(float2*)p = make_float2(acc[mt][nt][half * 2] * sc,
                                          acc[mt][nt][half * 2 + 1] * sc);
            }
        }
    }
}

// ========== output GEMM: 128x64 tile + bias + scatter ==========
__global__ __launch_bounds__(256, 1) void out_mma_kernel(
    const float* __restrict__ bo, const int* __restrict__ index,
    float* __restrict__ out) {
    __shared__ __nv_bfloat16 sAh[128][BP], sAl[128][BP];
    __shared__ __nv_bfloat16 sBh[32][BPB], sBl[32][BPB];
    const int tid = threadIdx.x, lane = tid & 31, wid = tid >> 5;
    const int wm = wid & 1, wn = wid >> 1;
    const int cb = blockIdx.x * 64, row0 = blockIdx.y * 128;

    const int ar = tid >> 1, akb = (tid & 1) << 4;
    const int bkr = tid & 31, bnf = (tid >> 5) << 3;
    const __nv_bfloat16* gah = g_oh + (size_t)(row0 + ar) * DIMM + akb;
    const __nv_bfloat16* gal = g_ol + (size_t)(row0 + ar) * DIMM + akb;
    const __nv_bfloat16* gbh = g_woh + (size_t)bkr * DIMM + cb + bnf;
    const __nv_bfloat16* gbl = g_wol + (size_t)bkr * DIMM + cb + bnf;

    float acc[4][2][4] = {};

    uint4 rah  = *(const uint4*)(gah);
    uint4 rah2 = *(const uint4*)(gah + 8);
    uint4 ral  = *(const uint4*)(gal);
    uint4 ral2 = *(const uint4*)(gal + 8);
    uint4 rbh  = *(const uint4*)(gbh);
    uint4 rbl  = *(const uint4*)(gbl);

    for (int c = 0; c < 16; c++) {
        *(uint4*)&sAh[ar][akb]     = rah;
        *(uint4*)&sAh[ar][akb + 8] = rah2;
        *(uint4*)&sAl[ar][akb]     = ral;
        *(uint4*)&sAl[ar][akb + 8] = ral2;
        *(uint4*)&sBh[bkr][bnf] = rbh;
        *(uint4*)&sBl[bkr][bnf] = rbl;
        __syncthreads();
        if (c + 1 < 16) {
            const int k0 = (c + 1) * 32;
            rah  = *(const uint4*)(gah + k0);
            rah2 = *(const uint4*)(gah + k0 + 8);
            ral  = *(const uint4*)(gal + k0);
            ral2 = *(const uint4*)(gal + k0 + 8);
            rbh  = *(const uint4*)(gbh + (size_t)k0 * DIMM);
            rbl  = *(const uint4*)(gbl + (size_t)k0 * DIMM);
        }
#pragma unroll
        for (int ks = 0; ks < 2; ks++) {
            uint32_t ah[4][4], al[4][4], bh[2][2], bl[2][2];
            const int acol = ks * 16 + ((lane >> 4) << 3);
            const int krow = ks * 16 + (lane & 15);
#pragma unroll
            for (int mt = 0; mt < 4; mt++) {
                int arw = wm * 64 + mt * 16 + (lane & 15);
                ldmx4(ah[mt], (uint32_t)__cvta_generic_to_shared(&sAh[arw][acol]));
                ldmx4(al[mt], (uint32_t)__cvta_generic_to_shared(&sAl[arw][acol]));
            }
#pragma unroll
            for (int nt = 0; nt < 2; nt++) {
                int n0 = wn * 16 + nt * 8;
                ldmx2t(bh[nt], (uint32_t)__cvta_generic_to_shared(&sBh[krow][n0]));
                ldmx2t(bl[nt], (uint32_t)__cvta_generic_to_shared(&sBl[krow][n0]));
            }
#pragma unroll
            for (int mt = 0; mt < 4; mt++)
#pragma unroll
                for (int nt = 0; nt < 2; nt++) {
                    mma16816(acc[mt][nt], ah[mt], bh[nt]);
                    mma16816(acc[mt][nt], ah[mt], bl[nt]);
                    mma16816(acc[mt][nt], al[mt], bh[nt]);
                }
        }
        __syncthreads();
    }

#pragma unroll
    for (int mt = 0; mt < 4; mt++) {
#pragma unroll
        for (int nt = 0; nt < 2; nt++) {
            int n = cb + wn * 16 + nt * 8 + (lane & 3) * 2;
            float b0 = bo[n], b1 = bo[n + 1];
#pragma unroll
            for (int half = 0; half < 2; half++) {
                int r = row0 + wm * 64 + mt * 16 + (lane >> 2) + half * 8;
                int b = r >> 14, i = r & (NN - 1);
                int orow = b * NN + index[i];
                *(float2*)(out + (size_t)orow * DIMM + n) =
                    make_float2(acc[mt][nt][half * 2] + b0, acc[mt][nt][half * 2 + 1] + b1);
            }
        }
    }
}

// ------------------ landmarks: 4-way row-parallel segment means -------------
__global__ __launch_bounds__(256) void landmarks_kernel() {
    __shared__ float rq[4][64], rk[4][64];
    int j = blockIdx.x, bh = blockIdx.y;
    int d = threadIdx.x & 63, g = threadIdx.x >> 6;
    int s = g_segoff[j], e = g_segoff[j + 1];
    const float* qb = g_q + (size_t)bh * NN * DD;
    const float* kb = g_k + (size_t)bh * NN * DD;
    float sq = 0.f, sk = 0.f;
    for (int i = s + g; i < e; i += 4) {
        sq += qb[(size_t)i * DD + d];
        sk += kb[(size_t)i * DD + d];
    }
    rq[g][d] = sq; rk[g][d] = sk;
    __syncthreads();
    if (g == 0) {
        float tq = rq[0][d] + rq[1][d] + rq[2][d] + rq[3][d];
        float tk = rk[0][d] + rk[1][d] + rk[2][d] + rk[3][d];
        g_ql[((size_t)bh * LL + j) * DD + d] = tq * (1.0f / 64.0f);
        g_kl[((size_t)bh * LL + j) * DD + d] = tk * (1.0f / 64.0f);
    }
}

// ------------------ attn2 = softmax(q_l k_l^T) ------------------
__global__ __launch_bounds__(256) void attn2_kernel() {
    __shared__ float skl[LL * DD];
    __shared__ float ss[LL * 66];
    int bh = blockIdx.x, tid = threadIdx.x;
    for (int e = tid; e < LL * DD; e += 256) skl[e] = g_kl[(size_t)bh * LL * DD + e];
    __syncthreads();
    const float* qb = g_ql + (size_t)bh * LL * DD;
    for (int e = tid; e < LL * LL; e += 256) {
        int i = e / LL, j = e - i * LL;
        float s = 0.f;
        for (int d = 0; d < DD; d += 4) {
            float4 a = *(const float4*)(qb + i * DD + d);
            float4 b = *(float4*)&skl[j * DD + d];
            s += a.x * b.x + a.y * b.y + a.z * b.z + a.w * b.w;
        }
        ss[i * 66 + j] = s;
    }
    __syncthreads();
    int warp = tid >> 5, lane = tid & 31;
    for (int r = warp; r < LL; r += 8) {
        float mx = -1e30f;
        for (int j = lane; j < LL; j += 32) mx = fmaxf(mx, ss[r * 66 + j]);
        for (int o = 16; o; o >>= 1) mx = fmaxf(mx, __shfl_xor_sync(~0u, mx, o));
        float sum = 0.f;
        for (int j = lane; j < LL; j += 32) {
            float p = expf(ss[r * 66 + j] - mx);
            ss[r * 66 + j] = p; sum += p;
        }
        for (int o = 16; o; o >>= 1) sum += __shfl_xor_sync(~0u, sum, o);
        float inv = 1.f / sum;
        for (int j = lane; j < LL; j += 32)
            g_attn2[((size_t)bh * LL + r) * LL + j] = ss[r * 66 + j] * inv;
    }
}

// ------------------ global scalar ------------------
__global__ __launch_bounds__(256) void scal_kernel() {
    __shared__ float redc[256], redr[256];
    int tid = threadIdx.x;
    float mc = 0.f, mr = 0.f;
    for (int e = tid; e < BHH * LL; e += 256) {
        int bh = e / LL, i = e - bh * LL;
        const float* Xb = g_attn2 + (size_t)bh * LL * LL;
        float rs = 0.f, cs = 0.f;
        for (int j = 0; j < LL; j++) {
            rs += fabsf(Xb[i * LL + j]);
            cs += fabsf(Xb[j * LL + i]);
        }
        mc = fmaxf(mc, rs); mr = fmaxf(mr, cs);
    }
    redc[tid] = mc; redr[tid] = mr;
    __syncthreads();
    for (int s = 128; s > 0; s >>= 1) {
        if (tid < s) {
            redc[tid] = fmaxf(redc[tid], redc[tid + s]);
            redr[tid] = fmaxf(redr[tid], redr[tid + s]);
        }
        __syncthreads();
    }
    if (tid == 0) g_scal[0] = redc[0] * redr[0];
}

// ------------------ Moore-Penrose pinv ------------------
__device__ __forceinline__ void smm65(const float* __restrict__ P,
                                      const float* __restrict__ Q,
                                      float* __restrict__ O,
                                      float beta, float sgn, int tid) {
    for (int t = tid; t < 17 * 17; t += 256) {
        int tr = (t / 17) * 4, tc = (t % 17) * 4;
        float c[4][4] = {};
        for (int k = 0; k < LL; k++) {
            float a[4], b[4];
#pragma unroll
            for (int u = 0; u < 4; u++) { a[u] = P[(tr + u) * 68 + k]; b[u] = Q[k * 68 + tc + u]; }
#pragma unroll
            for (int u = 0; u < 4; u++)
#pragma unroll
                for (int v = 0; v < 4; v++) c[u][v] += a[u] * b[v];
        }
#pragma unroll
        for (int u = 0; u < 4; u++) {
            int i = tr + u; if (i >= LL) continue;
#pragma unroll
            for (int v = 0; v < 4; v++) {
                int j = tc + v; if (j >= LL) continue;
                O[i * 68 + j] = beta * P[i * 68 + j] + sgn * c[u][v];
            }
        }
    }
}

#define PMS (68 * 68)
#define PINV_SMEM (5 * PMS * 4)
__global__ __launch_bounds__(256) void pinv_kernel() {
    extern __shared__ float sm[];
    float* X = sm; float* Z = sm + PMS; float* A_ = sm + 2 * PMS;
    float* Bf = sm + 3 * PMS; float* Cf = sm + 4 * PMS;
    int bh = blockIdx.x, tid = threadIdx.x;
    for (int e = tid; e < 5 * PMS; e += 256) sm[e] = 0.f;
    __syncthreads();
    const float* Xg = g_attn2 + (size_t)bh * LL * LL;
    for (int e = tid; e < LL * LL; e += 256) {
        int i = e / LL, j = e - i * LL;
        X[i * 68 + j] = Xg[e];
    }
    __syncthreads();
    float inva = 1.0f / g_scal[0];
    for (int e = tid; e < LL * LL; e += 256) {
        int i = e / LL, j = e - i * LL;
        Z[i * 68 + j] = X[j * 68 + i] * inva;
    }
    __syncthreads();
    for (int it = 0; it < 6; it++) {
        smm65(X, Z, A_, 0.f, 1.f, tid);  __syncthreads();
        smm65(A_, A_, Bf, 7.f, -1.f, tid); __syncthreads();
        smm65(A_, Bf, Cf, 15.f, -1.f, tid); __syncthreads();
        smm65(Z, Cf, A_, 13.f, -1.f, tid); __syncthreads();
        for (int e = tid; e < LL * LL; e += 256) {
            int i = e / LL, j = e - i * LL;
            Z[i * 68 + j] = 0.25f * A_[i * 68 + j];
        }
        __syncthreads();
    }
    for (int e = tid; e < LL * LL; e += 256) {
        int i = e / LL, j = e - i * LL;
        g_z[(size_t)bh * LL * LL + e] = Z[i * 68 + j];
    }
}

// ------------------ split flash pass (pitch-68, blocked, multi-row PV) ------
#define SPLIT_SMEM ((LL*68 + 64*68 + 64*DD + LL*DD + LL*66 + 3*LL) * 4)
__global__ __launch_bounds__(256) void split_kernel() {
    extern __shared__ float sm[];
    float* sQ = sm;
    float* sK = sQ + LL * 68;
    float* sV = sK + 64 * 68;
    float* accm = sV + 64 * DD;
    float* sS = accm + LL * DD;
    float* mrow = sS + LL * 66;
    float* lrow = mrow + LL;
    float* frow = lrow + LL;
    int sp = blockIdx.x, bh = blockIdx.y, tid = threadIdx.x;
    const float* Kb = g_k + (size_t)bh * NN * DD;
    const float* Vb = g_v + (size_t)bh * NN * DD;
    const float* Qg = g_ql + (size_t)bh * LL * DD;
    for (int e = tid; e < LL * 16; e += 256) {
        int r = e >> 4, c = (e & 15) << 2;
        *(float4*)&sQ[r * 68 + c] = *(const float4*)(Qg + r * DD + c);
    }
    for (int e = tid; e < LL * DD; e += 256) accm[e] = 0.f;
    if (tid < LL) { mrow[tid] = -1e30f; lrow[tid] = 0.f; }
    __syncthreads();
    int warp = tid >> 5, lane = tid & 31;
    for (int t = 0; t < CHUNK / 64; t++) {
        int i0 = sp * CHUNK + t * 64;
        for (int e = tid; e < 64 * 16; e += 256) {
            int r = e >> 4, c = (e & 15) << 2;
            *(float4*)&sK[r * 68 + c] = *(const float4*)(Kb + (size_t)(i0 + r) * DD + c);
            *(float4*)&sV[r * DD + c] = *(const float4*)(Vb + (size_t)(i0 + r) * DD + c);
        }
        __syncthreads();
        for (int e = tid; e < LL * 16; e += 256) {
            int r = e >> 4, iq = (e & 15) << 2;
            float s0 = 0.f, s1 = 0.f, s2 = 0.f, s3 = 0.f;
            for (int d = 0; d < DD; d += 4) {
                float4 a = *(float4*)&sQ[r * 68 + d];
                float4 b0 = *(float4*)&sK[(iq + 0) * 68 + d];
                float4 b1 = *(float4*)&sK[(iq + 1) * 68 + d];
                float4 b2 = *(float4*)&sK[(iq + 2) * 68 + d];
                float4 b3 = *(float4*)&sK[(iq + 3) * 68 + d];
                s0 += a.x * b0.x + a.y * b0.y + a.z * b0.z + a.w * b0.w;
                s1 += a.x * b1.x + a.y * b1.y + a.z * b1.z + a.w * b1.w;
                s2 += a.x * b2.x + a.y * b2.y + a.z * b2.z + a.w * b2.w;
                s3 += a.x * b3.x + a.y * b3.y + a.z * b3.z + a.w * b3.w;
            }
            sS[r * 66 + iq + 0] = s0; sS[r * 66 + iq + 1] = s1;
            sS[r * 66 + iq + 2] = s2; sS[r * 66 + iq + 3] = s3;
        }
        __syncthreads();
        for (int r = warp; r < LL; r += 8) {
            float mx = -1e30f;
            for (int i = lane; i < 64; i += 32) mx = fmaxf(mx, sS[r * 66 + i]);
            for (int o = 16; o; o >>= 1) mx = fmaxf(mx, __shfl_xor_sync(~0u, mx, o));
            float mnew = fmaxf(mrow[r], mx);
            float sum = 0.f;
            for (int i = lane; i < 64; i += 32) {
                float p = expf(sS[r * 66 + i] - mnew);
                sS[r * 66 + i] = p; sum += p;
            }
            for (int o = 16; o; o >>= 1) sum += __shfl_xor_sync(~0u, sum, o);
            if (lane == 0) {
                float f = expf(mrow[r] - mnew);
                frow[r] = f;
                lrow[r] = lrow[r] * f + sum;
                mrow[r] = mnew;
            }
        }
        __syncthreads();
        {
            int r = tid >> 4, c = (tid & 15) << 2;
            int r2 = r + 32, r3 = r + 16, r4 = r + 48;
            float f1 = frow[r], f2 = frow[r2], f3 = frow[r3], f4 = frow[r4];
            float4 a1 = *(float4*)&accm[r * DD + c];
            float4 a2 = *(float4*)&accm[r2 * DD + c];
            float4 a3 = *(float4*)&accm[r3 * DD + c];
            float4 a4 = *(float4*)&accm[r4 * DD + c];
            a1.x *= f1; a1.y *= f1; a1.z *= f1; a1.w *= f1;
            a2.x *= f2; a2.y *= f2; a2.z *= f2; a2.w *= f2;
            a3.x *= f3; a3.y *= f3; a3.z *= f3; a3.w *= f3;
            a4.x *= f4; a4.y *= f4; a4.z *= f4; a4.w *= f4;
            for (int i = 0; i < 64; i++) {
                float4 vv = *(float4*)&sV[i * DD + c];
                float p1 = sS[r * 66 + i], p2 = sS[r2 * 66 + i];
                float p3 = sS[r3 * 66 + i], p4 = sS[r4 * 66 + i];
                a1.x += p1 * vv.x; a1.y += p1 * vv.y; a1.z += p1 * vv.z; a1.w += p1 * vv.w;
                a2.x += p2 * vv.x; a2.y += p2 * vv.y; a2.z += p2 * vv.z; a2.w += p2 * vv.w;
                a3.x += p3 * vv.x; a3.y += p3 * vv.y; a3.z += p3 * vv.z; a3.w += p3 * vv.w;
                a4.x += p4 * vv.x; a4.y += p4 * vv.y; a4.z += p4 * vv.z; a4.w += p4 * vv.w;
            }
            *(float4*)&accm[r * DD + c] = a1;
            *(float4*)&accm[r2 * DD + c] = a2;
            *(float4*)&accm[r3 * DD + c] = a3;
            *(float4*)&accm[r4 * DD + c] = a4;
        }
        if (tid < 16) {
            int c = tid << 2;
            float f = frow[64];
            float4 a = *(float4*)&accm[64 * DD + c];
            a.x *= f; a.y *= f; a.z *= f; a.w *= f;
            for (int i = 0; i < 64; i++) {
                float p = sS[64 * 66 + i];
                float4 vv = *(float4*)&sV[i * DD + c];
                a.x += p * vv.x; a.y += p * vv.y; a.z += p * vv.z; a.w += p * vv.w;
            }
            *(float4*)&accm[64 * DD + c] = a;
        }
        __syncthreads();
    }
    size_t pb = (size_t)(bh * NSPLIT + sp);
    for (int e = tid; e < LL * DD; e += 256) g_pacc[pb * LL * DD + e] = accm[e];
    if (tid < LL) { g_pm[pb * LL + tid] = mrow[tid]; g_pl[pb * LL + tid] = lrow[tid]; }
}

// ------------------ combine ------------------
__global__ void combine_kernel() {
    int j = blockIdx.x, bh = blockIdx.y, d = threadIdx.x;
    float M = -1e30f;
    for (int s = 0; s < NSPLIT; s++)
        M = fmaxf(M, g_pm[((size_t)(bh * NSPLIT + s)) * LL + j]);
    float lsum = 0.f, a = 0.f;
    for (int s = 0; s < NSPLIT; s++) {
        size_t pb = (size_t)(bh * NSPLIT + s);
        float w = expf(g_pm[pb * LL + j] - M);
        lsum += w * g_pl[pb * LL + j];
        a += w * g_pacc[(pb * LL + j) * DD + d];
    }
    g_tmp1[((size_t)bh * LL + j) * DD + d] = a / lsum;
}

// ------------------ tmp2 = z @ tmp1 ------------------
__global__ __launch_bounds__(256) void tmp2_kernel() {
    __shared__ float sT[LL * DD];
    __shared__ float sZ[LL * 68];
    int bh = blockIdx.x, tid = threadIdx.x;
    for (int e = tid; e < LL * DD; e += 256) sT[e] = g_tmp1[(size_t)bh * LL * DD + e];
    for (int e = tid; e < LL * LL; e += 256) {
        int i = e / LL, j = e - i * LL;
        sZ[i * 68 + j] = g_z[(size_t)bh * LL * LL + e];
    }
    __syncthreads();
    for (int e = tid; e < LL * 16; e += 256) {
        int j = e >> 4, c = (e & 15) << 2;
        float4 acc = make_float4(0.f, 0.f, 0.f, 0.f);
        for (int m = 0; m < LL; m++) {
            float z = sZ[j * 68 + m];
            float4 t = *(float4*)&sT[m * DD + c];
            acc.x += z * t.x; acc.y += z * t.y; acc.z += z * t.z; acc.w += z * t.w;
        }
        *(float4*)(g_tmp2 + (size_t)bh * LL * DD + j * DD + c) = acc;
    }
}

// ------------------ fused final: emits bf16 hi/lo (union-free) --------------
#define FINAL_SMEM ((68*68 + LL*68 + 32*68 + 64*DD + 32*66 + 36 + 32) * 4)
__global__ __launch_bounds__(256) void final_kernel(const float* __restrict__ wres) {
    extern __shared__ float sm[];
    float* sKL = sm;
    float* sT2 = sKL + 68 * 68;
    float* sQ2 = sT2 + LL * 68;
    float* sVs = sQ2 + 32 * 68;
    float* sS  = sVs + 64 * DD;
    float* sw  = sS + 32 * 66;
    float* sinv = sw + 36;
    int it = blockIdx.x, bh = blockIdx.y, tid = threadIdx.x;
    int hd = bh & 7, b = bh >> 3;
    int i0 = it * 32;
    const float* KLg = g_kl + (size_t)bh * LL * DD;
    const float* T2g = g_tmp2 + (size_t)bh * LL * DD;
    for (int e = tid; e < LL * 16; e += 256) {
        int r = e >> 4, c = (e & 15) << 2;
        *(float4*)&sKL[r * 68 + c] = *(const float4*)(KLg + r * DD + c);
        *(float4*)&sT2[r * 68 + c] = *(const float4*)(T2g + r * DD + c);
    }
    for (int e = tid; e < 3 * 68; e += 256) sKL[65 * 68 + e] = 0.f;
    for (int e = tid; e < 32 * 16; e += 256) {
        int r = e >> 4, c = (e & 15) << 2;
        *(float4*)&sQ2[r * 68 + c] =
            *(const float4*)(g_q + ((size_t)bh * NN + i0 + r) * DD + c);
    }
    for (int e = tid; e < 64 * 16; e += 256) {
        int r = e >> 4, c = (e & 15) << 2;
        int gi = i0 - 16 + r;
        float4 vv = make_float4(0.f, 0.f, 0.f, 0.f);
        if (gi >= 0 && gi < NN) vv = *(const float4*)(g_v + ((size_t)bh * NN + gi) * DD + c);
        *(float4*)&sVs[r * DD + c] = vv;
    }
    if (tid < 33) sw[tid] = wres[hd * 33 + tid];
    __syncthreads();
    for (int e = tid; e < 32 * 17; e += 256) {
        int r = e / 17, jq = (e - r * 17) << 2;
        float s0 = 0.f, s1 = 0.f, s2 = 0.f, s3 = 0.f;
        for (int d = 0; d < DD; d += 4) {
            float4 a = *(float4*)&sQ2[r * 68 + d];
            float4 b0 = *(float4*)&sKL[(jq + 0) * 68 + d];
            float4 b1 = *(float4*)&sKL[(jq + 1) * 68 + d];
            float4 b2 = *(float4*)&sKL[(jq + 2) * 68 + d];
            float4 b3 = *(float4*)&sKL[(jq + 3) * 68 + d];
            s0 += a.x * b0.x + a.y * b0.y + a.z * b0.z + a.w * b0.w;
            s1 += a.x * b1.x + a.y * b1.y + a.z * b1.z + a.w * b1.w;
            s2 += a.x * b2.x + a.y * b2.y + a.z * b2.z + a.w * b2.w;
            s3 += a.x * b3.x + a.y * b3.y + a.z * b3.z + a.w * b3.w;
        }
        if (jq < 64) {
            sS[r * 66 + jq + 0] = s0; sS[r * 66 + jq + 1] = s1;
            sS[r * 66 + jq + 2] = s2; sS[r * 66 + jq + 3] = s3;
        } else {
            sS[r * 66 + 64] = s0;
        }
    }
    __syncthreads();
    int warp = tid >> 5, lane = tid & 31;
    for (int r = warp; r < 32; r += 8) {
        float mx = -1e30f;
        for (int j = lane; j < LL; j += 32) mx = fmaxf(mx, sS[r * 66 + j]);
        for (int o = 16; o; o >>= 1) mx = fmaxf(mx, __shfl_xor_sync(~0u, mx, o));
        float sum = 0.f;
        for (int j = lane; j < LL; j += 32) {
            float p = expf(sS[r * 66 + j] - mx);
            sS[r * 66 + j] = p; sum += p;
        }
        for (int o = 16; o; o >>= 1) sum += __shfl_xor_sync(~0u, sum, o);
        if (lane == 0) sinv[r] = 1.f / sum;
    }
    __syncthreads();
    {
        int r = tid >> 4, c = (tid & 15) << 2;
        int r2 = r + 16;
        float4 a1 = make_float4(0.f, 0.f, 0.f, 0.f);
        float4 a2 = make_float4(0.f, 0.f, 0.f, 0.f);
        for (int j = 0; j < LL; j++) {
            float4 t = *(float4*)&sT2[j * 68 + c];
            float p1 = sS[r * 66 + j], p2 = sS[r2 * 66 + j];
            a1.x += p1 * t.x; a1.y += p1 * t.y; a1.z += p1 * t.z; a1.w += p1 * t.w;
            a2.x += p2 * t.x; a2.y += p2 * t.y; a2.z += p2 * t.z; a2.w += p2 * t.w;
        }
        float i1 = sinv[r], i2 = sinv[r2];
        a1.x *= i1; a1.y *= i1; a1.z *= i1; a1.w *= i1;
        a2.x *= i2; a2.y *= i2; a2.z *= i2; a2.w *= i2;
        for (int k = 0; k < 33; k++) {
            float wv = sw[k];
            float4 v1 = *(float4*)&sVs[(r + k) * DD + c];
            float4 v2 = *(float4*)&sVs[(r2 + k) * DD + c];
            a1.x += wv * v1.x; a1.y += wv * v1.y; a1.z += wv * v1.z; a1.w += wv * v1.w;
            a2.x += wv * v2.x; a2.y += wv * v2.y; a2.z += wv * v2.z; a2.w += wv * v2.w;
        }
        __nv_bfloat16 h0, h1, h2, h3, l0, l1, l2, l3;
        size_t off1 = ((size_t)b * NN + i0 + r) * DIMM + hd * DD + c;
        size_t off2 = ((size_t)b * NN + i0 + r2) * DIMM + hd * DD + c;
        bf_split(a1.x, h0, l0); bf_split(a1.y, h1, l1);
        bf_split(a1.z, h2, l2); bf_split(a1.w, h3, l3);
        *(uint2*)(g_oh + off1) = make_uint2(pack2(h0, h1), pack2(h2, h3));
        *(uint2*)(g_ol + off1) = make_uint2(pack2(l0, l1), pack2(l2, l3));
        bf_split(a2.x, h0, l0); bf_split(a2.y, h1, l1);
        bf_split(a2.z, h2, l2); bf_split(a2.w, h3, l3);
        *(uint2*)(g_oh + off2) = make_uint2(pack2(h0, h1), pack2(h2, h3));
        *(uint2*)(g_ol + off2) = make_uint2(pack2(l0, l1), pack2(l2, l3));
    }
}

// ------------------ launch ------------------
extern "C" void kernel_launch(void* const* d_in, const int* in_sizes, int n_in,
                              void* d_out, int out_size) {
    const float* x     = (const float*)d_in[0];
    const int*   index = (const int*)d_in[1];
    const int*   seg   = (const int*)d_in[3];
    const float* wqkv  = (const float*)d_in[4];
    const float* wout  = (const float*)d_in[5];
    const float* bout  = (const float*)d_in[6];
    const float* wres  = (const float*)d_in[7];
    float* out = (float*)d_out;

    __nv_bfloat16 *p_wqh, *p_wql, *p_woh, *p_wol;
    cudaGetSymbolAddress((void**)&p_wqh, g_wqh);
    cudaGetSymbolAddress((void**)&p_wql, g_wql);
    cudaGetSymbolAddress((void**)&p_woh, g_woh);
    cudaGetSymbolAddress((void**)&p_wol, g_wol);

    cudaFuncSetAttribute(pinv_kernel,  cudaFuncAttributeMaxDynamicSharedMemorySize, PINV_SMEM);
    cudaFuncSetAttribute(split_kernel, cudaFuncAttributeMaxDynamicSharedMemorySize, SPLIT_SMEM);
    cudaFuncSetAttribute(final_kernel, cudaFuncAttributeMaxDynamicSharedMemorySize, FINAL_SMEM);

    seg_init_kernel<<<1, 128>>>();
    seg_count_kernel<<<64, 256>>>(seg);
    seg_scan_kernel<<<1, 32>>>();
    conv_x_kernel<<<8192, 256>>>(x, index);
    conv_w_kernel<<<384, 256>>>(wqkv, p_wqh, p_wql);
    conv_w_kernel<<<128, 256>>>(wout, p_woh, p_wol);
    qkv_mma_kernel<<<dim3(24, 256), 256>>>();
    landmarks_kernel<<<dim3(LL, BHH), 256>>>();
    attn2_kernel<<<BHH, 256>>>();
    scal_kernel<<<1, 256>>>();
    pinv_kernel<<<BHH, 256, PINV_SMEM>>>();
    split_kernel<<<dim3(NSPLIT, BHH), 256, SPLIT_SMEM>>>();
    combine_kernel<<<dim3(LL, BHH), 64>>>();
    tmp2_kernel<<<BHH, 256>>>();
    final_kernel<<<dim3(NN / 32, BHH), 256, FINAL_SMEM>>>(wres);
    out_mma_kernel<<<dim3(8, 256), 256>>>(bout, index, out);
}

// round 14
// speedup vs baseline: 1.0911x; 1.0911x over previous
#include <cuda_runtime.h>
#include <cuda_bf16.h>
#include <cstdint>
#include <math.h>

#define NN 16384
#define HH 8
#define DD 64
#define LL 65
#define BHH 16
#define NSPLIT 16
#define CHUNK 1024
#define DIMM 512
#define QKVN 1536

// ------------------ device scratch (allocation-free rule) -------------------
__device__ float g_q[(size_t)BHH * NN * DD];
__device__ float g_k[(size_t)BHH * NN * DD];
__device__ float g_v[(size_t)BHH * NN * DD];
__device__ float g_ql[BHH * LL * DD];
__device__ float g_kl[BHH * LL * DD];
__device__ float g_attn2[BHH * LL * LL];
__device__ float g_z[BHH * LL * LL];
__device__ float g_scal[1];
__device__ float g_pm[BHH * NSPLIT * LL];
__device__ float g_pl[BHH * NSPLIT * LL];
__device__ float g_pacc[BHH * NSPLIT * LL * DD];
__device__ float g_tmp1[BHH * LL * DD];
__device__ float g_tmp2[BHH * LL * DD];
__device__ int   g_segcnt[LL];
__device__ int   g_segoff[LL + 1];
// bf16 hi/lo staging
__device__ __nv_bfloat16 g_xqh[(size_t)2 * NN * DIMM];
__device__ __nv_bfloat16 g_xql[(size_t)2 * NN * DIMM];
__device__ __nv_bfloat16 g_wqh[DIMM * QKVN];
__device__ __nv_bfloat16 g_wql[DIMM * QKVN];
__device__ __nv_bfloat16 g_oh[(size_t)2 * NN * DIMM];
__device__ __nv_bfloat16 g_ol[(size_t)2 * NN * DIMM];
__device__ __nv_bfloat16 g_woh[DIMM * DIMM];
__device__ __nv_bfloat16 g_wol[DIMM * DIMM];

// ================== mma.sync helpers =========
__device__ __forceinline__ void mma16816(float* c, const uint32_t* a, const uint32_t* b) {
    asm volatile(
        "mma.sync.aligned.m16n8k16.row.col.f32.bf16.bf16.f32 "
        "{%0,%1,%2,%3}, {%4,%5,%6,%7}, {%8,%9}, {%0,%1,%2,%3};"
        : "+f"(c[0]), "+f"(c[1]), "+f"(c[2]), "+f"(c[3])
        : "r"(a[0]), "r"(a[1]), "r"(a[2]), "r"(a[3]), "r"(b[0]), "r"(b[1]));
}
__device__ __forceinline__ void ldmx4(uint32_t* r, uint32_t addr) {
    asm volatile("ldmatrix.sync.aligned.m8n8.x4.shared.b16 {%0,%1,%2,%3}, [%4];"
                 : "=r"(r[0]), "=r"(r[1]), "=r"(r[2]), "=r"(r[3]) : "r"(addr));
}
__device__ __forceinline__ void ldmx2t(uint32_t* r, uint32_t addr) {
    asm volatile("ldmatrix.sync.aligned.m8n8.x2.trans.shared.b16 {%0,%1}, [%2];"
                 : "=r"(r[0]), "=r"(r[1]) : "r"(addr));
}
__device__ __forceinline__ void bf_split(float v, __nv_bfloat16& h, __nv_bfloat16& l) {
    h = __float2bfloat16(v);
    l = __float2bfloat16(v - __bfloat162float(h));
}
__device__ __forceinline__ uint32_t pack2(__nv_bfloat16 a, __nv_bfloat16 b) {
    return (uint32_t)__bfloat16_as_ushort(a) | ((uint32_t)__bfloat16_as_ushort(b) << 16);
}

#define BP 40    // A smem row pitch (bf16 elems)
#define BPB 136  // B smem row pitch (bf16 elems), k-major 32x136
// dynamic smem layout per stage (bf16 elems):
//   Ah @0 (128x40=5120), Al @5120, Bh @10240 (32x136=4352), Bl @14592
#define STG 18944
#define GEMM_SMEM (2 * STG * 2)   // bytes

// ------------------ segment offsets ------------------
__global__ void seg_init_kernel() { if (threadIdx.x < LL) g_segcnt[threadIdx.x] = 0; }
__global__ void seg_count_kernel(const int* __restrict__ seg) {
    int i = blockIdx.x * 256 + threadIdx.x;
    if (i < NN) atomicAdd(&g_segcnt[seg[i]], 1);
}
__global__ void seg_scan_kernel() {
    if (threadIdx.x == 0) {
        int acc = 0;
        for (int j = 0; j < LL; j++) { g_segoff[j] = acc; acc += g_segcnt[j]; }
        g_segoff[LL] = acc;
    }
}

// ------------------ conversion kernels (union-free) ------------------
__global__ __launch_bounds__(256) void conv_x_kernel(
    const float* __restrict__ x, const int* __restrict__ index) {
    size_t idx = ((size_t)blockIdx.x * 256 + threadIdx.x) * 8;
    int r = (int)(idx >> 9), c = (int)(idx & 511);
    int b = r >> 14, i = r & (NN - 1);
    int ar = b * NN + index[i];
    const float* s = x + (size_t)ar * DIMM + c;
    float4 v0 = *(const float4*)s, v1 = *(const float4*)(s + 4);
    __nv_bfloat16 h0, h1, h2, h3, h4, h5, h6, h7;
    __nv_bfloat16 l0, l1, l2, l3, l4, l5, l6, l7;
    bf_split(v0.x, h0, l0); bf_split(v0.y, h1, l1);
    bf_split(v0.z, h2, l2); bf_split(v0.w, h3, l3);
    bf_split(v1.x, h4, l4); bf_split(v1.y, h5, l5);
    bf_split(v1.z, h6, l6); bf_split(v1.w, h7, l7);
    uint4 H = make_uint4(pack2(h0, h1), pack2(h2, h3), pack2(h4, h5), pack2(h6, h7));
    uint4 L = make_uint4(pack2(l0, l1), pack2(l2, l3), pack2(l4, l5), pack2(l6, l7));
    *(uint4*)(g_xqh + idx) = H;
    *(uint4*)(g_xql + idx) = L;
}
__global__ __launch_bounds__(256) void conv_w_kernel(
    const float* __restrict__ src, __nv_bfloat16* __restrict__ dh,
    __nv_bfloat16* __restrict__ dl) {
    size_t idx = ((size_t)blockIdx.x * 256 + threadIdx.x) * 8;
    float4 v0 = *(const float4*)(src + idx), v1 = *(const float4*)(src + idx + 4);
    __nv_bfloat16 h0, h1, h2, h3, h4, h5, h6, h7;
    __nv_bfloat16 l0, l1, l2, l3, l4, l5, l6, l7;
    bf_split(v0.x, h0, l0); bf_split(v0.y, h1, l1);
    bf_split(v0.z, h2, l2); bf_split(v0.w, h3, l3);
    bf_split(v1.x, h4, l4); bf_split(v1.y, h5, l5);
    bf_split(v1.z, h6, l6); bf_split(v1.w, h7, l7);
    uint4 H = make_uint4(pack2(h0, h1), pack2(h2, h3), pack2(h4, h5), pack2(h6, h7));
    uint4 L = make_uint4(pack2(l0, l1), pack2(l2, l3), pack2(l4, l5), pack2(l6, l7));
    *(uint4*)(dh + idx) = H;
    *(uint4*)(dl + idx) = L;
}

// ========== QKV GEMM: 128x128 tile, double-buffered smem, reg prefetch ======
__global__ __launch_bounds__(256, 1) void qkv_mma_kernel() {
    extern __shared__ __nv_bfloat16 smg[];
    const int tid = threadIdx.x, lane = tid & 31, wid = tid >> 5;
    const int wm = wid & 1, wn = wid >> 1;
    const int cb = blockIdx.x * 128, row0 = blockIdx.y * 128;

    const int ar = tid >> 1, akb = (tid & 1) << 4;
    const int bkr = tid & 31, bnf = (tid >> 5) << 4;
    const __nv_bfloat16* gah = g_xqh + (size_t)(row0 + ar) * DIMM + akb;
    const __nv_bfloat16* gal = g_xql + (size_t)(row0 + ar) * DIMM + akb;
    const __nv_bfloat16* gbh = g_wqh + (size_t)bkr * QKVN + cb + bnf;
    const __nv_bfloat16* gbl = g_wql + (size_t)bkr * QKVN + cb + bnf;

    float acc[4][4][4] = {};

    uint4 rah, rah2, ral, ral2, rbh, rbh2, rbl, rbl2;
    rah  = *(const uint4*)(gah);
    rah2 = *(const uint4*)(gah + 8);
    ral  = *(const uint4*)(gal);
    ral2 = *(const uint4*)(gal + 8);
    rbh  = *(const uint4*)(gbh);
    rbh2 = *(const uint4*)(gbh + 8);
    rbl  = *(const uint4*)(gbl);
    rbl2 = *(const uint4*)(gbl + 8);
    {
        __nv_bfloat16* bs = smg;
        *(uint4*)(bs + ar * BP + akb)            = rah;
        *(uint4*)(bs + ar * BP + akb + 8)        = rah2;
        *(uint4*)(bs + 5120 + ar * BP + akb)     = ral;
        *(uint4*)(bs + 5120 + ar * BP + akb + 8) = ral2;
        *(uint4*)(bs + 10240 + bkr * BPB + bnf)     = rbh;
        *(uint4*)(bs + 10240 + bkr * BPB + bnf + 8) = rbh2;
        *(uint4*)(bs + 14592 + bkr * BPB + bnf)     = rbl;
        *(uint4*)(bs + 14592 + bkr * BPB + bnf + 8) = rbl2;
    }
    __syncthreads();

    for (int c = 0; c < 16; c++) {
        if (c + 1 < 16) {
            const int k0 = (c + 1) * 32;
            rah  = *(const uint4*)(gah + k0);
            rah2 = *(const uint4*)(gah + k0 + 8);
            ral  = *(const uint4*)(gal + k0);
            ral2 = *(const uint4*)(gal + k0 + 8);
            rbh  = *(const uint4*)(gbh + (size_t)k0 * QKVN);
            rbh2 = *(const uint4*)(gbh + (size_t)k0 * QKVN + 8);
            rbl  = *(const uint4*)(gbl + (size_t)k0 * QKVN);
            rbl2 = *(const uint4*)(gbl + (size_t)k0 * QKVN + 8);
        }
        __nv_bfloat16* bs = smg + (c & 1) * STG;
#pragma unroll
        for (int ks = 0; ks < 2; ks++) {
            uint32_t ah[4][4], al[4][4], bh[4][2], bl[4][2];
            const int acol = ks * 16 + ((lane >> 4) << 3);
            const int krow = ks * 16 + (lane & 15);
#pragma unroll
            for (int mt = 0; mt < 4; mt++) {
                int arw = wm * 64 + mt * 16 + (lane & 15);
                ldmx4(ah[mt], (uint32_t)__cvta_generic_to_shared(bs + arw * BP + acol));
                ldmx4(al[mt], (uint32_t)__cvta_generic_to_shared(bs + 5120 + arw * BP + acol));
            }
#pragma unroll
            for (int nt = 0; nt < 4; nt++) {
                int n0 = wn * 32 + nt * 8;
                ldmx2t(bh[nt], (uint32_t)__cvta_generic_to_shared(bs + 10240 + krow * BPB + n0));
                ldmx2t(bl[nt], (uint32_t)__cvta_generic_to_shared(bs + 14592 + krow * BPB + n0));
            }
#pragma unroll
            for (int mt = 0; mt < 4; mt++)
#pragma unroll
                for (int nt = 0; nt < 4; nt++) {
                    mma16816(acc[mt][nt], ah[mt], bh[nt]);
                    mma16816(acc[mt][nt], ah[mt], bl[nt]);
                    mma16816(acc[mt][nt], al[mt], bh[nt]);
                }
        }
        if (c + 1 < 16) {
            __nv_bfloat16* ns = smg + ((c + 1) & 1) * STG;
            *(uint4*)(ns + ar * BP + akb)            = rah;
            *(uint4*)(ns + ar * BP + akb + 8)        = rah2;
            *(uint4*)(ns + 5120 + ar * BP + akb)     = ral;
            *(uint4*)(ns + 5120 + ar * BP + akb + 8) = ral2;
            *(uint4*)(ns + 10240 + bkr * BPB + bnf)     = rbh;
            *(uint4*)(ns + 10240 + bkr * BPB + bnf + 8) = rbh2;
            *(uint4*)(ns + 14592 + bkr * BPB + bnf)     = rbl;
            *(uint4*)(ns + 14592 + bkr * BPB + bnf + 8) = rbl2;
            __syncthreads();
        }
    }

    const int part = cb >> 9;
    float* dst = part == 0 ? g_q : (part == 1 ? g_k : g_v);
    const float sc = part == 0 ? 0.125f : 1.f;
#pragma unroll
    for (int mt = 0; mt < 4; mt++) {
#pragma unroll
        for (int nt = 0; nt < 4; nt++) {
            int n = cb + wn * 32 + nt * 8 + (lane & 3) * 2;
            int hd = (n >> 6) & 7, d0 = n & 63;
#pragma unroll
            for (int half = 0; half < 2; half++) {
                int r = row0 + wm * 64 + mt * 16 + (lane >> 2) + half * 8;
                int b = r >> 14, i = r & (NN - 1);
                float* p = dst + ((size_t)(b * HH + hd) * NN + i) * DD + d0;
                *(float2*)p = make_float2(acc[mt][nt][half * 2] * sc,
                                          acc[mt][nt][half * 2 + 1] * sc);
            }
        }
    }
}

// ========== output GEMM: double-buffered + bias + scatter ==========
__global__ __launch_bounds__(256, 1) void out_mma_kernel(
    const float* __restrict__ bo, const int* __restrict__ index,
    float* __restrict__ out) {
    extern __shared__ __nv_bfloat16 smg[];
    const int tid = threadIdx.x, lane = tid & 31, wid = tid >> 5;
    const int wm = wid & 1, wn = wid >> 1;
    const int cb = blockIdx.x * 128, row0 = blockIdx.y * 128;

    const int ar = tid >> 1, akb = (tid & 1) << 4;
    const int bkr = tid & 31, bnf = (tid >> 5) << 4;
    const __nv_bfloat16* gah = g_oh + (size_t)(row0 + ar) * DIMM + akb;
    const __nv_bfloat16* gal = g_ol + (size_t)(row0 + ar) * DIMM + akb;
    const __nv_bfloat16* gbh = g_woh + (size_t)bkr * DIMM + cb + bnf;
    const __nv_bfloat16* gbl = g_wol + (size_t)bkr * DIMM + cb + bnf;

    float acc[4][4][4] = {};

    uint4 rah, rah2, ral, ral2, rbh, rbh2, rbl, rbl2;
    rah  = *(const uint4*)(gah);
    rah2 = *(const uint4*)(gah + 8);
    ral  = *(const uint4*)(gal);
    ral2 = *(const uint4*)(gal + 8);
    rbh  = *(const uint4*)(gbh);
    rbh2 = *(const uint4*)(gbh + 8);
    rbl  = *(const uint4*)(gbl);
    rbl2 = *(const uint4*)(gbl + 8);
    {
        __nv_bfloat16* bs = smg;
        *(uint4*)(bs + ar * BP + akb)            = rah;
        *(uint4*)(bs + ar * BP + akb + 8)        = rah2;
        *(uint4*)(bs + 5120 + ar * BP + akb)     = ral;
        *(uint4*)(bs + 5120 + ar * BP + akb + 8) = ral2;
        *(uint4*)(bs + 10240 + bkr * BPB + bnf)     = rbh;
        *(uint4*)(bs + 10240 + bkr * BPB + bnf + 8) = rbh2;
        *(uint4*)(bs + 14592 + bkr * BPB + bnf)     = rbl;
        *(uint4*)(bs + 14592 + bkr * BPB + bnf + 8) = rbl2;
    }
    __syncthreads();

    for (int c = 0; c < 16; c++) {
        if (c + 1 < 16) {
            const int k0 = (c + 1) * 32;
            rah  = *(const uint4*)(gah + k0);
            rah2 = *(const uint4*)(gah + k0 + 8);
            ral  = *(const uint4*)(gal + k0);
            ral2 = *(const uint4*)(gal + k0 + 8);
            rbh  = *(const uint4*)(gbh + (size_t)k0 * DIMM);
            rbh2 = *(const uint4*)(gbh + (size_t)k0 * DIMM + 8);
            rbl  = *(const uint4*)(gbl + (size_t)k0 * DIMM);
            rbl2 = *(const uint4*)(gbl + (size_t)k0 * DIMM + 8);
        }
        __nv_bfloat16* bs = smg + (c & 1) * STG;
#pragma unroll
        for (int ks = 0; ks < 2; ks++) {
            uint32_t ah[4][4], al[4][4], bh[4][2], bl[4][2];
            const int acol = ks * 16 + ((lane >> 4) << 3);
            const int krow = ks * 16 + (lane & 15);
#pragma unroll
            for (int mt = 0; mt < 4; mt++) {
                int arw = wm * 64 + mt * 16 + (lane & 15);
                ldmx4(ah[mt], (uint32_t)__cvta_generic_to_shared(bs + arw * BP + acol));
                ldmx4(al[mt], (uint32_t)__cvta_generic_to_shared(bs + 5120 + arw * BP + acol));
            }
#pragma unroll
            for (int nt = 0; nt < 4; nt++) {
                int n0 = wn * 32 + nt * 8;
                ldmx2t(bh[nt], (uint32_t)__cvta_generic_to_shared(bs + 10240 + krow * BPB + n0));
                ldmx2t(bl[nt], (uint32_t)__cvta_generic_to_shared(bs + 14592 + krow * BPB + n0));
            }
#pragma unroll
            for (int mt = 0; mt < 4; mt++)
#pragma unroll
                for (int nt = 0; nt < 4; nt++) {
                    mma16816(acc[mt][nt], ah[mt], bh[nt]);
                    mma16816(acc[mt][nt], ah[mt], bl[nt]);
                    mma16816(acc[mt][nt], al[mt], bh[nt]);
                }
        }
        if (c + 1 < 16) {
            __nv_bfloat16* ns = smg + ((c + 1) & 1) * STG;
            *(uint4*)(ns + ar * BP + akb)            = rah;
            *(uint4*)(ns + ar * BP + akb + 8)        = rah2;
            *(uint4*)(ns + 5120 + ar * BP + akb)     = ral;
            *(uint4*)(ns + 5120 + ar * BP + akb + 8) = ral2;
            *(uint4*)(ns + 10240 + bkr * BPB + bnf)     = rbh;
            *(uint4*)(ns + 10240 + bkr * BPB + bnf + 8) = rbh2;
            *(uint4*)(ns + 14592 + bkr * BPB + bnf)     = rbl;
            *(uint4*)(ns + 14592 + bkr * BPB + bnf + 8) = rbl2;
            __syncthreads();
        }
    }

#pragma unroll
    for (int mt = 0; mt < 4; mt++) {
#pragma unroll
        for (int nt = 0; nt < 4; nt++) {
            int n = cb + wn * 32 + nt * 8 + (lane & 3) * 2;
            float b0 = bo[n], b1 = bo[n + 1];
#pragma unroll
            for (int half = 0; half < 2; half++) {
                int r = row0 + wm * 64 + mt * 16 + (lane >> 2) + half * 8;
                int b = r >> 14, i = r & (NN - 1);
                int orow = b * NN + index[i];
                *(float2*)(out + (size_t)orow * DIMM + n) =
                    make_float2(acc[mt][nt][half * 2] + b0, acc[mt][nt][half * 2 + 1] + b1);
            }
        }
    }
}

// ------------------ landmarks: 4-way row-parallel segment means -------------
__global__ __launch_bounds__(256) void landmarks_kernel() {
    __shared__ float rq[4][64], rk[4][64];
    int j = blockIdx.x, bh = blockIdx.y;
    int d = threadIdx.x & 63, g = threadIdx.x >> 6;
    int s = g_segoff[j], e = g_segoff[j + 1];
    const float* qb = g_q + (size_t)bh * NN * DD;
    const float* kb = g_k + (size_t)bh * NN * DD;
    float sq = 0.f, sk = 0.f;
    for (int i = s + g; i < e; i += 4) {
        sq += qb[(size_t)i * DD + d];
        sk += kb[(size_t)i * DD + d];
    }
    rq[g][d] = sq; rk[g][d] = sk;
    __syncthreads();
    if (g == 0) {
        float tq = rq[0][d] + rq[1][d] + rq[2][d] + rq[3][d];
        float tk = rk[0][d] + rk[1][d] + rk[2][d] + rk[3][d];
        g_ql[((size_t)bh * LL + j) * DD + d] = tq * (1.0f / 64.0f);
        g_kl[((size_t)bh * LL + j) * DD + d] = tk * (1.0f / 64.0f);
    }
}

// ------------------ attn2 = softmax(q_l k_l^T) ------------------
__global__ __launch_bounds__(256) void attn2_kernel() {
    __shared__ float skl[LL * DD];
    __shared__ float ss[LL * 66];
    int bh = blockIdx.x, tid = threadIdx.x;
    for (int e = tid; e < LL * DD; e += 256) skl[e] = g_kl[(size_t)bh * LL * DD + e];
    __syncthreads();
    const float* qb = g_ql + (size_t)bh * LL * DD;
    for (int e = tid; e < LL * LL; e += 256) {
        int i = e / LL, j = e - i * LL;
        float s = 0.f;
        for (int d = 0; d < DD; d += 4) {
            float4 a = *(const float4*)(qb + i * DD + d);
            float4 b = *(float4*)&skl[j * DD + d];
            s += a.x * b.x + a.y * b.y + a.z * b.z + a.w * b.w;
        }
        ss[i * 66 + j] = s;
    }
    __syncthreads();
    int warp = tid >> 5, lane = tid & 31;
    for (int r = warp; r < LL; r += 8) {
        float mx = -1e30f;
        for (int j = lane; j < LL; j += 32) mx = fmaxf(mx, ss[r * 66 + j]);
        for (int o = 16; o; o >>= 1) mx = fmaxf(mx, __shfl_xor_sync(~0u, mx, o));
        float sum = 0.f;
        for (int j = lane; j < LL; j += 32) {
            float p = expf(ss[r * 66 + j] - mx);
            ss[r * 66 + j] = p; sum += p;
        }
        for (int o = 16; o; o >>= 1) sum += __shfl_xor_sync(~0u, sum, o);
        float inv = 1.f / sum;
        for (int j = lane; j < LL; j += 32)
            g_attn2[((size_t)bh * LL + r) * LL + j] = ss[r * 66 + j] * inv;
    }
}

// ------------------ global scalar ------------------
__global__ __launch_bounds__(256) void scal_kernel() {
    __shared__ float redc[256], redr[256];
    int tid = threadIdx.x;
    float mc = 0.f, mr = 0.f;
    for (int e = tid; e < BHH * LL; e += 256) {
        int bh = e / LL, i = e - bh * LL;
        const float* Xb = g_attn2 + (size_t)bh * LL * LL;
        float rs = 0.f, cs = 0.f;
        for (int j = 0; j < LL; j++) {
            rs += fabsf(Xb[i * LL + j]);
            cs += fabsf(Xb[j * LL + i]);
        }
        mc = fmaxf(mc, rs); mr = fmaxf(mr, cs);
    }
    redc[tid] = mc; redr[tid] = mr;
    __syncthreads();
    for (int s = 128; s > 0; s >>= 1) {
        if (tid < s) {
            redc[tid] = fmaxf(redc[tid], redc[tid + s]);
            redr[tid] = fmaxf(redr[tid], redr[tid + s]);
        }
        __syncthreads();
    }
    if (tid == 0) g_scal[0] = redc[0] * redr[0];
}

// ------------------ Moore-Penrose pinv ------------------
__device__ __forceinline__ void smm65(const float* __restrict__ P,
                                      const float* __restrict__ Q,
                                      float* __restrict__ O,
                                      float beta, float sgn, int tid) {
    for (int t = tid; t < 17 * 17; t += 256) {
        int tr = (t / 17) * 4, tc = (t % 17) * 4;
        float c[4][4] = {};
        for (int k = 0; k < LL; k++) {
            float a[4], b[4];
#pragma unroll
            for (int u = 0; u < 4; u++) { a[u] = P[(tr + u) * 68 + k]; b[u] = Q[k * 68 + tc + u]; }
#pragma unroll
            for (int u = 0; u < 4; u++)
#pragma unroll
                for (int v = 0; v < 4; v++) c[u][v] += a[u] * b[v];
        }
#pragma unroll
        for (int u = 0; u < 4; u++) {
            int i = tr + u; if (i >= LL) continue;
#pragma unroll
            for (int v = 0; v < 4; v++) {
                int j = tc + v; if (j >= LL) continue;
                O[i * 68 + j] = beta * P[i * 68 + j] + sgn * c[u][v];
            }
        }
    }
}

#define PMS (68 * 68)
#define PINV_SMEM (5 * PMS * 4)
__global__ __launch_bounds__(256) void pinv_kernel() {
    extern __shared__ float sm[];
    float* X = sm; float* Z = sm + PMS; float* A_ = sm + 2 * PMS;
    float* Bf = sm + 3 * PMS; float* Cf = sm + 4 * PMS;
    int bh = blockIdx.x, tid = threadIdx.x;
    for (int e = tid; e < 5 * PMS; e += 256) sm[e] = 0.f;
    __syncthreads();
    const float* Xg = g_attn2 + (size_t)bh * LL * LL;
    for (int e = tid; e < LL * LL; e += 256) {
        int i = e / LL, j = e - i * LL;
        X[i * 68 + j] = Xg[e];
    }
    __syncthreads();
    float inva = 1.0f / g_scal[0];
    for (int e = tid; e < LL * LL; e += 256) {
        int i = e / LL, j = e - i * LL;
        Z[i * 68 + j] = X[j * 68 + i] * inva;
    }
    __syncthreads();
    for (int it = 0; it < 6; it++) {
        smm65(X, Z, A_, 0.f, 1.f, tid);  __syncthreads();
        smm65(A_, A_, Bf, 7.f, -1.f, tid); __syncthreads();
        smm65(A_, Bf, Cf, 15.f, -1.f, tid); __syncthreads();
        smm65(Z, Cf, A_, 13.f, -1.f, tid); __syncthreads();
        for (int e = tid; e < LL * LL; e += 256) {
            int i = e / LL, j = e - i * LL;
            Z[i * 68 + j] = 0.25f * A_[i * 68 + j];
        }
        __syncthreads();
    }
    for (int e = tid; e < LL * LL; e += 256) {
        int i = e / LL, j = e - i * LL;
        g_z[(size_t)bh * LL * LL + e] = Z[i * 68 + j];
    }
}

// ------------------ split flash pass (pitch-68, blocked, multi-row PV) ------
#define SPLIT_SMEM ((LL*68 + 64*68 + 64*DD + LL*DD + LL*66 + 3*LL) * 4)
__global__ __launch_bounds__(256) void split_kernel() {
    extern __shared__ float sm[];
    float* sQ = sm;
    float* sK = sQ + LL * 68;
    float* sV = sK + 64 * 68;
    float* accm = sV + 64 * DD;
    float* sS = accm + LL * DD;
    float* mrow = sS + LL * 66;
    float* lrow = mrow + LL;
    float* frow = lrow + LL;
    int sp = blockIdx.x, bh = blockIdx.y, tid = threadIdx.x;
    const float* Kb = g_k + (size_t)bh * NN * DD;
    const float* Vb = g_v + (size_t)bh * NN * DD;
    const float* Qg = g_ql + (size_t)bh * LL * DD;
    for (int e = tid; e < LL * 16; e += 256) {
        int r = e >> 4, c = (e & 15) << 2;
        *(float4*)&sQ[r * 68 + c] = *(const float4*)(Qg + r * DD + c);
    }
    for (int e = tid; e < LL * DD; e += 256) accm[e] = 0.f;
    if (tid < LL) { mrow[tid] = -1e30f; lrow[tid] = 0.f; }
    __syncthreads();
    int warp = tid >> 5, lane = tid & 31;
    for (int t = 0; t < CHUNK / 64; t++) {
        int i0 = sp * CHUNK + t * 64;
        for (int e = tid; e < 64 * 16; e += 256) {
            int r = e >> 4, c = (e & 15) << 2;
            *(float4*)&sK[r * 68 + c] = *(const float4*)(Kb + (size_t)(i0 + r) * DD + c);
            *(float4*)&sV[r * DD + c] = *(const float4*)(Vb + (size_t)(i0 + r) * DD + c);
        }
        __syncthreads();
        for (int e = tid; e < LL * 16; e += 256) {
            int r = e >> 4, iq = (e & 15) << 2;
            float s0 = 0.f, s1 = 0.f, s2 = 0.f, s3 = 0.f;
            for (int d = 0; d < DD; d += 4) {
                float4 a = *(float4*)&sQ[r * 68 + d];
                float4 b0 = *(float4*)&sK[(iq + 0) * 68 + d];
                float4 b1 = *(float4*)&sK[(iq + 1) * 68 + d];
                float4 b2 = *(float4*)&sK[(iq + 2) * 68 + d];
                float4 b3 = *(float4*)&sK[(iq + 3) * 68 + d];
                s0 += a.x * b0.x + a.y * b0.y + a.z * b0.z + a.w * b0.w;
                s1 += a.x * b1.x + a.y * b1.y + a.z * b1.z + a.w * b1.w;
                s2 += a.x * b2.x + a.y * b2.y + a.z * b2.z + a.w * b2.w;
                s3 += a.x * b3.x + a.y * b3.y + a.z * b3.z + a.w * b3.w;
            }
            sS[r * 66 + iq + 0] = s0; sS[r * 66 + iq + 1] = s1;
            sS[r * 66 + iq + 2] = s2; sS[r * 66 + iq + 3] = s3;
        }
        __syncthreads();
        for (int r = warp; r < LL; r += 8) {
            float mx = -1e30f;
            for (int i = lane; i < 64; i += 32) mx = fmaxf(mx, sS[r * 66 + i]);
            for (int o = 16; o; o >>= 1) mx = fmaxf(mx, __shfl_xor_sync(~0u, mx, o));
            float mnew = fmaxf(mrow[r], mx);
            float sum = 0.f;
            for (int i = lane; i < 64; i += 32) {
                float p = expf(sS[r * 66 + i] - mnew);
                sS[r * 66 + i] = p; sum += p;
            }
            for (int o = 16; o; o >>= 1) sum += __shfl_xor_sync(~0u, sum, o);
            if (lane == 0) {
                float f = expf(mrow[r] - mnew);
                frow[r] = f;
                lrow[r] = lrow[r] * f + sum;
                mrow[r] = mnew;
            }
        }
        __syncthreads();
        {
            int r = tid >> 4, c = (tid & 15) << 2;
            int r2 = r + 32, r3 = r + 16, r4 = r + 48;
            float f1 = frow[r], f2 = frow[r2], f3 = frow[r3], f4 = frow[r4];
            float4 a1 = *(float4*)&accm[r * DD + c];
            float4 a2 = *(float4*)&accm[r2 * DD + c];
            float4 a3 = *(float4*)&accm[r3 * DD + c];
            float4 a4 = *(float4*)&accm[r4 * DD + c];
            a1.x *= f1; a1.y *= f1; a1.z *= f1; a1.w *= f1;
            a2.x *= f2; a2.y *= f2; a2.z *= f2; a2.w *= f2;
            a3.x *= f3; a3.y *= f3; a3.z *= f3; a3.w *= f3;
            a4.x *= f4; a4.y *= f4; a4.z *= f4; a4.w *= f4;
            for (int i = 0; i < 64; i++) {
                float4 vv = *(float4*)&sV[i * DD + c];
                float p1 = sS[r * 66 + i], p2 = sS[r2 * 66 + i];
                float p3 = sS[r3 * 66 + i], p4 = sS[r4 * 66 + i];
                a1.x += p1 * vv.x; a1.y += p1 * vv.y; a1.z += p1 * vv.z; a1.w += p1 * vv.w;
                a2.x += p2 * vv.x; a2.y += p2 * vv.y; a2.z += p2 * vv.z; a2.w += p2 * vv.w;
                a3.x += p3 * vv.x; a3.y += p3 * vv.y; a3.z += p3 * vv.z; a3.w += p3 * vv.w;
                a4.x += p4 * vv.x; a4.y += p4 * vv.y; a4.z += p4 * vv.z; a4.w += p4 * vv.w;
            }
            *(float4*)&accm[r * DD + c] = a1;
            *(float4*)&accm[r2 * DD + c] = a2;
            *(float4*)&accm[r3 * DD + c] = a3;
            *(float4*)&accm[r4 * DD + c] = a4;
        }
        if (tid < 16) {
            int c = tid << 2;
            float f = frow[64];
            float4 a = *(float4*)&accm[64 * DD + c];
            a.x *= f; a.y *= f; a.z *= f; a.w *= f;
            for (int i = 0; i < 64; i++) {
                float p = sS[64 * 66 + i];
                float4 vv = *(float4*)&sV[i * DD + c];
                a.x += p * vv.x; a.y += p * vv.y; a.z += p * vv.z; a.w += p * vv.w;
            }
            *(float4*)&accm[64 * DD + c] = a;
        }
        __syncthreads();
    }
    size_t pb = (size_t)(bh * NSPLIT + sp);
    for (int e = tid; e < LL * DD; e += 256) g_pacc[pb * LL * DD + e] = accm[e];
    if (tid < LL) { g_pm[pb * LL + tid] = mrow[tid]; g_pl[pb * LL + tid] = lrow[tid]; }
}

// ------------------ combine ------------------
__global__ void combine_kernel() {
    int j = blockIdx.x, bh = blockIdx.y, d = threadIdx.x;
    float M = -1e30f;
    for (int s = 0; s < NSPLIT; s++)
        M = fmaxf(M, g_pm[((size_t)(bh * NSPLIT + s)) * LL + j]);
    float lsum = 0.f, a = 0.f;
    for (int s = 0; s < NSPLIT; s++) {
        size_t pb = (size_t)(bh * NSPLIT + s);
        float w = expf(g_pm[pb * LL + j] - M);
        lsum += w * g_pl[pb * LL + j];
        a += w * g_pacc[(pb * LL + j) * DD + d];
    }
    g_tmp1[((size_t)bh * LL + j) * DD + d] = a / lsum;
}

// ------------------ tmp2 = z @ tmp1 ------------------
__global__ __launch_bounds__(256) void tmp2_kernel() {
    __shared__ float sT[LL * DD];
    __shared__ float sZ[LL * 68];
    int bh = blockIdx.x, tid = threadIdx.x;
    for (int e = tid; e < LL * DD; e += 256) sT[e] = g_tmp1[(size_t)bh * LL * DD + e];
    for (int e = tid; e < LL * LL; e += 256) {
        int i = e / LL, j = e - i * LL;
        sZ[i * 68 + j] = g_z[(size_t)bh * LL * LL + e];
    }
    __syncthreads();
    for (int e = tid; e < LL * 16; e += 256) {
        int j = e >> 4, c = (e & 15) << 2;
        float4 acc = make_float4(0.f, 0.f, 0.f, 0.f);
        for (int m = 0; m < LL; m++) {
            float z = sZ[j * 68 + m];
            float4 t = *(float4*)&sT[m * DD + c];
            acc.x += z * t.x; acc.y += z * t.y; acc.z += z * t.z; acc.w += z * t.w;
        }
        *(float4*)(g_tmp2 + (size_t)bh * LL * DD + j * DD + c) = acc;
    }
}

// ------------------ fused final: emits bf16 hi/lo (union-free) --------------
#define FINAL_SMEM ((68*68 + LL*68 + 32*68 + 64*DD + 32*66 + 36 + 32) * 4)
__global__ __launch_bounds__(256) void final_kernel(const float* __restrict__ wres) {
    extern __shared__ float sm[];
    float* sKL = sm;
    float* sT2 = sKL + 68 * 68;
    float* sQ2 = sT2 + LL * 68;
    float* sVs = sQ2 + 32 * 68;
    float* sS  = sVs + 64 * DD;
    float* sw  = sS + 32 * 66;
    float* sinv = sw + 36;
    int it = blockIdx.x, bh = blockIdx.y, tid = threadIdx.x;
    int hd = bh & 7, b = bh >> 3;
    int i0 = it * 32;
    const float* KLg = g_kl + (size_t)bh * LL * DD;
    const float* T2g = g_tmp2 + (size_t)bh * LL * DD;
    for (int e = tid; e < LL * 16; e += 256) {
        int r = e >> 4, c = (e & 15) << 2;
        *(float4*)&sKL[r * 68 + c] = *(const float4*)(KLg + r * DD + c);
        *(float4*)&sT2[r * 68 + c] = *(const float4*)(T2g + r * DD + c);
    }
    for (int e = tid; e < 3 * 68; e += 256) sKL[65 * 68 + e] = 0.f;
    for (int e = tid; e < 32 * 16; e += 256) {
        int r = e >> 4, c = (e & 15) << 2;
        *(float4*)&sQ2[r * 68 + c] =
            *(const float4*)(g_q + ((size_t)bh * NN + i0 + r) * DD + c);
    }
    for (int e = tid; e < 64 * 16; e += 256) {
        int r = e >> 4, c = (e & 15) << 2;
        int gi = i0 - 16 + r;
        float4 vv = make_float4(0.f, 0.f, 0.f, 0.f);
        if (gi >= 0 && gi < NN) vv = *(const float4*)(g_v + ((size_t)bh * NN + gi) * DD + c);
        *(float4*)&sVs[r * DD + c] = vv;
    }
    if (tid < 33) sw[tid] = wres[hd * 33 + tid];
    __syncthreads();
    for (int e = tid; e < 32 * 17; e += 256) {
        int r = e / 17, jq = (e - r * 17) << 2;
        float s0 = 0.f, s1 = 0.f, s2 = 0.f, s3 = 0.f;
        for (int d = 0; d < DD; d += 4) {
            float4 a = *(float4*)&sQ2[r * 68 + d];
            float4 b0 = *(float4*)&sKL[(jq + 0) * 68 + d];
            float4 b1 = *(float4*)&sKL[(jq + 1) * 68 + d];
            float4 b2 = *(float4*)&sKL[(jq + 2) * 68 + d];
            float4 b3 = *(float4*)&sKL[(jq + 3) * 68 + d];
            s0 += a.x * b0.x + a.y * b0.y + a.z * b0.z + a.w * b0.w;
            s1 += a.x * b1.x + a.y * b1.y + a.z * b1.z + a.w * b1.w;
            s2 += a.x * b2.x + a.y * b2.y + a.z * b2.z + a.w * b2.w;
            s3 += a.x * b3.x + a.y * b3.y + a.z * b3.z + a.w * b3.w;
        }
        if (jq < 64) {
            sS[r * 66 + jq + 0] = s0; sS[r * 66 + jq + 1] = s1;
            sS[r * 66 + jq + 2] = s2; sS[r * 66 + jq + 3] = s3;
        } else {
            sS[r * 66 + 64] = s0;
        }
    }
    __syncthreads();
    int warp = tid >> 5, lane = tid & 31;
    for (int r = warp; r < 32; r += 8) {
        float mx = -1e30f;
        for (int j = lane; j < LL; j += 32) mx = fmaxf(mx, sS[r * 66 + j]);
        for (int o = 16; o; o >>= 1) mx = fmaxf(mx, __shfl_xor_sync(~0u, mx, o));
        float sum = 0.f;
        for (int j = lane; j < LL; j += 32) {
            float p = expf(sS[r * 66 + j] - mx);
            sS[r * 66 + j] = p; sum += p;
        }
        for (int o = 16; o; o >>= 1) sum += __shfl_xor_sync(~0u, sum, o);
        if (lane == 0) sinv[r] = 1.f / sum;
    }
    __syncthreads();
    {
        int r = tid >> 4, c = (tid & 15) << 2;
        int r2 = r + 16;
        float4 a1 = make_float4(0.f, 0.f, 0.f, 0.f);
        float4 a2 = make_float4(0.f, 0.f, 0.f, 0.f);
        for (int j = 0; j < LL; j++) {
            float4 t = *(float4*)&sT2[j * 68 + c];
            float p1 = sS[r * 66 + j], p2 = sS[r2 * 66 + j];
            a1.x += p1 * t.x; a1.y += p1 * t.y; a1.z += p1 * t.z; a1.w += p1 * t.w;
            a2.x += p2 * t.x; a2.y += p2 * t.y; a2.z += p2 * t.z; a2.w += p2 * t.w;
        }
        float i1 = sinv[r], i2 = sinv[r2];
        a1.x *= i1; a1.y *= i1; a1.z *= i1; a1.w *= i1;
        a2.x *= i2; a2.y *= i2; a2.z *= i2; a2.w *= i2;
        for (int k = 0; k < 33; k++) {
            float wv = sw[k];
            float4 v1 = *(float4*)&sVs[(r + k) * DD + c];
            float4 v2 = *(float4*)&sVs[(r2 + k) * DD + c];
            a1.x += wv * v1.x; a1.y += wv * v1.y; a1.z += wv * v1.z; a1.w += wv * v1.w;
            a2.x += wv * v2.x; a2.y += wv * v2.y; a2.z += wv * v2.z; a2.w += wv * v2.w;
        }
        __nv_bfloat16 h0, h1, h2, h3, l0, l1, l2, l3;
        size_t off1 = ((size_t)b * NN + i0 + r) * DIMM + hd * DD + c;
        size_t off2 = ((size_t)b * NN + i0 + r2) * DIMM + hd * DD + c;
        bf_split(a1.x, h0, l0); bf_split(a1.y, h1, l1);
        bf_split(a1.z, h2, l2); bf_split(a1.w, h3, l3);
        *(uint2*)(g_oh + off1) = make_uint2(pack2(h0, h1), pack2(h2, h3));
        *(uint2*)(g_ol + off1) = make_uint2(pack2(l0, l1), pack2(l2, l3));
        bf_split(a2.x, h0, l0); bf_split(a2.y, h1, l1);
        bf_split(a2.z, h2, l2); bf_split(a2.w, h3, l3);
        *(uint2*)(g_oh + off2) = make_uint2(pack2(h0, h1), pack2(h2, h3));
        *(uint2*)(g_ol + off2) = make_uint2(pack2(l0, l1), pack2(l2, l3));
    }
}

// ------------------ launch ------------------
extern "C" void kernel_launch(void* const* d_in, const int* in_sizes, int n_in,
                              void* d_out, int out_size) {
    const float* x     = (const float*)d_in[0];
    const int*   index = (const int*)d_in[1];
    const int*   seg   = (const int*)d_in[3];
    const float* wqkv  = (const float*)d_in[4];
    const float* wout  = (const float*)d_in[5];
    const float* bout  = (const float*)d_in[6];
    const float* wres  = (const float*)d_in[7];
    float* out = (float*)d_out;

    __nv_bfloat16 *p_wqh, *p_wql, *p_woh, *p_wol;
    cudaGetSymbolAddress((void**)&p_wqh, g_wqh);
    cudaGetSymbolAddress((void**)&p_wql, g_wql);
    cudaGetSymbolAddress((void**)&p_woh, g_woh);
    cudaGetSymbolAddress((void**)&p_wol, g_wol);

    cudaFuncSetAttribute(pinv_kernel,  cudaFuncAttributeMaxDynamicSharedMemorySize, PINV_SMEM);
    cudaFuncSetAttribute(split_kernel, cudaFuncAttributeMaxDynamicSharedMemorySize, SPLIT_SMEM);
    cudaFuncSetAttribute(final_kernel, cudaFuncAttributeMaxDynamicSharedMemorySize, FINAL_SMEM);
    cudaFuncSetAttribute(qkv_mma_kernel, cudaFuncAttributeMaxDynamicSharedMemorySize, GEMM_SMEM);
    cudaFuncSetAttribute(out_mma_kernel, cudaFuncAttributeMaxDynamicSharedMemorySize, GEMM_SMEM);

    seg_init_kernel<<<1, 128>>>();
    seg_count_kernel<<<64, 256>>>(seg);
    seg_scan_kernel<<<1, 32>>>();
    conv_x_kernel<<<8192, 256>>>(x, index);
    conv_w_kernel<<<384, 256>>>(wqkv, p_wqh, p_wql);
    conv_w_kernel<<<128, 256>>>(wout, p_woh, p_wol);
    qkv_mma_kernel<<<dim3(12, 256), 256, GEMM_SMEM>>>();
    landmarks_kernel<<<dim3(LL, BHH), 256>>>();
    attn2_kernel<<<BHH, 256>>>();
    scal_kernel<<<1, 256>>>();
    pinv_kernel<<<BHH, 256, PINV_SMEM>>>();
    split_kernel<<<dim3(NSPLIT, BHH), 256, SPLIT_SMEM>>>();
    combine_kernel<<<dim3(LL, BHH), 64>>>();
    tmp2_kernel<<<BHH, 256>>>();
    final_kernel<<<dim3(NN / 32, BHH), 256, FINAL_SMEM>>>(wres);
    out_mma_kernel<<<dim3(4, 256), 256, GEMM_SMEM>>>(bout, index, out);
}

// round 15
// speedup vs baseline: 1.5294x; 1.4017x over previous
#include <cuda_runtime.h>
#include <cuda_bf16.h>
#include <cstdint>
#include <math.h>

#define NN 16384
#define HH 8
#define DD 64
#define LL 65
#define BHH 16
#define NSPLIT 16
#define CHUNK 1024
#define DIMM 512
#define QKVN 1536

// ------------------ device scratch (allocation-free rule) -------------------
__device__ float g_q[(size_t)BHH * NN * DD];
__device__ float g_k[(size_t)BHH * NN * DD];
__device__ float g_v[(size_t)BHH * NN * DD];
__device__ float g_ql[BHH * LL * DD];
__device__ float g_kl[BHH * LL * DD];
__device__ float g_attn2[BHH * LL * LL];
__device__ float g_z[BHH * LL * LL];
__device__ float g_scal[1];
__device__ float g_pm[BHH * NSPLIT * LL];
__device__ float g_pl[BHH * NSPLIT * LL];
__device__ float g_pacc[BHH * NSPLIT * LL * DD];
__device__ float g_tmp1[BHH * LL * DD];
__device__ float g_tmp2[BHH * LL * DD];
__device__ int   g_segcnt[LL];
__device__ int   g_segoff[LL + 1];
// bf16 hi/lo staging
__device__ __nv_bfloat16 g_xqh[(size_t)2 * NN * DIMM];
__device__ __nv_bfloat16 g_xql[(size_t)2 * NN * DIMM];
__device__ __nv_bfloat16 g_wqh[DIMM * QKVN];
__device__ __nv_bfloat16 g_wql[DIMM * QKVN];
__device__ __nv_bfloat16 g_oh[(size_t)2 * NN * DIMM];
__device__ __nv_bfloat16 g_ol[(size_t)2 * NN * DIMM];
__device__ __nv_bfloat16 g_woh[DIMM * DIMM];
__device__ __nv_bfloat16 g_wol[DIMM * DIMM];

// ================== mma.sync helpers =========
__device__ __forceinline__ void mma16816(float* c, const uint32_t* a, const uint32_t* b) {
    asm volatile(
        "mma.sync.aligned.m16n8k16.row.col.f32.bf16.bf16.f32 "
        "{%0,%1,%2,%3}, {%4,%5,%6,%7}, {%8,%9}, {%0,%1,%2,%3};"
        : "+f"(c[0]), "+f"(c[1]), "+f"(c[2]), "+f"(c[3])
        : "r"(a[0]), "r"(a[1]), "r"(a[2]), "r"(a[3]), "r"(b[0]), "r"(b[1]));
}
__device__ __forceinline__ void ldmx4(uint32_t* r, uint32_t addr) {
    asm volatile("ldmatrix.sync.aligned.m8n8.x4.shared.b16 {%0,%1,%2,%3}, [%4];"
                 : "=r"(r[0]), "=r"(r[1]), "=r"(r[2]), "=r"(r[3]) : "r"(addr));
}
__device__ __forceinline__ void ldmx2t(uint32_t* r, uint32_t addr) {
    asm volatile("ldmatrix.sync.aligned.m8n8.x2.trans.shared.b16 {%0,%1}, [%2];"
                 : "=r"(r[0]), "=r"(r[1]) : "r"(addr));
}
__device__ __forceinline__ void bf_split(float v, __nv_bfloat16& h, __nv_bfloat16& l) {
    h = __float2bfloat16(v);
    l = __float2bfloat16(v - __bfloat162float(h));
}
__device__ __forceinline__ uint32_t pack2(__nv_bfloat16 a, __nv_bfloat16 b) {
    return (uint32_t)__bfloat16_as_ushort(a) | ((uint32_t)__bfloat16_as_ushort(b) << 16);
}

#define BP 40    // A smem row pitch (bf16 elems)
#define BPB 136  // B smem row pitch (bf16 elems), k-major 32x136
#define STG 18944
#define GEMM_SMEM (2 * STG * 2)   // bytes

// ------------------ segment offsets ------------------
__global__ void seg_init_kernel() { if (threadIdx.x < LL) g_segcnt[threadIdx.x] = 0; }
__global__ void seg_count_kernel(const int* __restrict__ seg) {
    int i = blockIdx.x * 256 + threadIdx.x;
    if (i < NN) atomicAdd(&g_segcnt[seg[i]], 1);
}
__global__ void seg_scan_kernel() {
    if (threadIdx.x == 0) {
        int acc = 0;
        for (int j = 0; j < LL; j++) { g_segoff[j] = acc; acc += g_segcnt[j]; }
        g_segoff[LL] = acc;
    }
}

// ------------------ conversion kernels (union-free) ------------------
__global__ __launch_bounds__(256) void conv_x_kernel(
    const float* __restrict__ x, const int* __restrict__ index) {
    size_t idx = ((size_t)blockIdx.x * 256 + threadIdx.x) * 8;
    int r = (int)(idx >> 9), c = (int)(idx & 511);
    int b = r >> 14, i = r & (NN - 1);
    int ar = b * NN + index[i];
    const float* s = x + (size_t)ar * DIMM + c;
    float4 v0 = *(const float4*)s, v1 = *(const float4*)(s + 4);
    __nv_bfloat16 h0, h1, h2, h3, h4, h5, h6, h7;
    __nv_bfloat16 l0, l1, l2, l3, l4, l5, l6, l7;
    bf_split(v0.x, h0, l0); bf_split(v0.y, h1, l1);
    bf_split(v0.z, h2, l2); bf_split(v0.w, h3, l3);
    bf_split(v1.x, h4, l4); bf_split(v1.y, h5, l5);
    bf_split(v1.z, h6, l6); bf_split(v1.w, h7, l7);
    uint4 H = make_uint4(pack2(h0, h1), pack2(h2, h3), pack2(h4, h5), pack2(h6, h7));
    uint4 L = make_uint4(pack2(l0, l1), pack2(l2, l3), pack2(l4, l5), pack2(l6, l7));
    *(uint4*)(g_xqh + idx) = H;
    *(uint4*)(g_xql + idx) = L;
}
__global__ __launch_bounds__(256) void conv_w_kernel(
    const float* __restrict__ src, __nv_bfloat16* __restrict__ dh,
    __nv_bfloat16* __restrict__ dl) {
    size_t idx = ((size_t)blockIdx.x * 256 + threadIdx.x) * 8;
    float4 v0 = *(const float4*)(src + idx), v1 = *(const float4*)(src + idx + 4);
    __nv_bfloat16 h0, h1, h2, h3, h4, h5, h6, h7;
    __nv_bfloat16 l0, l1, l2, l3, l4, l5, l6, l7;
    bf_split(v0.x, h0, l0); bf_split(v0.y, h1, l1);
    bf_split(v0.z, h2, l2); bf_split(v0.w, h3, l3);
    bf_split(v1.x, h4, l4); bf_split(v1.y, h5, l5);
    bf_split(v1.z, h6, l6); bf_split(v1.w, h7, l7);
    uint4 H = make_uint4(pack2(h0, h1), pack2(h2, h3), pack2(h4, h5), pack2(h6, h7));
    uint4 L = make_uint4(pack2(l0, l1), pack2(l2, l3), pack2(l4, l5), pack2(l6, l7));
    *(uint4*)(dh + idx) = H;
    *(uint4*)(dl + idx) = L;
}

// ========== QKV GEMM: 128x128 tile, double-buffered smem, reg prefetch ======
__global__ __launch_bounds__(256, 1) void qkv_mma_kernel() {
    extern __shared__ __nv_bfloat16 smg[];
    const int tid = threadIdx.x, lane = tid & 31, wid = tid >> 5;
    const int wm = wid & 1, wn = wid >> 1;
    const int cb = blockIdx.x * 128, row0 = blockIdx.y * 128;

    const int ar = tid >> 1, akb = (tid & 1) << 4;
    const int bkr = tid & 31, bnf = (tid >> 5) << 4;
    const __nv_bfloat16* gah = g_xqh + (size_t)(row0 + ar) * DIMM + akb;
    const __nv_bfloat16* gal = g_xql + (size_t)(row0 + ar) * DIMM + akb;
    const __nv_bfloat16* gbh = g_wqh + (size_t)bkr * QKVN + cb + bnf;
    const __nv_bfloat16* gbl = g_wql + (size_t)bkr * QKVN + cb + bnf;

    float acc[4][4][4] = {};

    uint4 rah, rah2, ral, ral2, rbh, rbh2, rbl, rbl2;
    rah  = *(const uint4*)(gah);
    rah2 = *(const uint4*)(gah + 8);
    ral  = *(const uint4*)(gal);
    ral2 = *(const uint4*)(gal + 8);
    rbh  = *(const uint4*)(gbh);
    rbh2 = *(const uint4*)(gbh + 8);
    rbl  = *(const uint4*)(gbl);
    rbl2 = *(const uint4*)(gbl + 8);
    {
        __nv_bfloat16* bs = smg;
        *(uint4*)(bs + ar * BP + akb)            = rah;
        *(uint4*)(bs + ar * BP + akb + 8)        = rah2;
        *(uint4*)(bs + 5120 + ar * BP + akb)     = ral;
        *(uint4*)(bs + 5120 + ar * BP + akb + 8) = ral2;
        *(uint4*)(bs + 10240 + bkr * BPB + bnf)     = rbh;
        *(uint4*)(bs + 10240 + bkr * BPB + bnf + 8) = rbh2;
        *(uint4*)(bs + 14592 + bkr * BPB + bnf)     = rbl;
        *(uint4*)(bs + 14592 + bkr * BPB + bnf + 8) = rbl2;
    }
    __syncthreads();

    for (int c = 0; c < 16; c++) {
        if (c + 1 < 16) {
            const int k0 = (c + 1) * 32;
            rah  = *(const uint4*)(gah + k0);
            rah2 = *(const uint4*)(gah + k0 + 8);
            ral  = *(const uint4*)(gal + k0);
            ral2 = *(const uint4*)(gal + k0 + 8);
            rbh  = *(const uint4*)(gbh + (size_t)k0 * QKVN);
            rbh2 = *(const uint4*)(gbh + (size_t)k0 * QKVN + 8);
            rbl  = *(const uint4*)(gbl + (size_t)k0 * QKVN);
            rbl2 = *(const uint4*)(gbl + (size_t)k0 * QKVN + 8);
        }
        __nv_bfloat16* bs = smg + (c & 1) * STG;
#pragma unroll
        for (int ks = 0; ks < 2; ks++) {
            uint32_t ah[4][4], al[4][4], bh[4][2], bl[4][2];
            const int acol = ks * 16 + ((lane >> 4) << 3);
            const int krow = ks * 16 + (lane & 15);
#pragma unroll
            for (int mt = 0; mt < 4; mt++) {
                int arw = wm * 64 + mt * 16 + (lane & 15);
                ldmx4(ah[mt], (uint32_t)__cvta_generic_to_shared(bs + arw * BP + acol));
                ldmx4(al[mt], (uint32_t)__cvta_generic_to_shared(bs + 5120 + arw * BP + acol));
            }
#pragma unroll
            for (int nt = 0; nt < 4; nt++) {
                int n0 = wn * 32 + nt * 8;
                ldmx2t(bh[nt], (uint32_t)__cvta_generic_to_shared(bs + 10240 + krow * BPB + n0));
                ldmx2t(bl[nt], (uint32_t)__cvta_generic_to_shared(bs + 14592 + krow * BPB + n0));
            }
#pragma unroll
            for (int mt = 0; mt < 4; mt++)
#pragma unroll
                for (int nt = 0; nt < 4; nt++) {
                    mma16816(acc[mt][nt], ah[mt], bh[nt]);
                    mma16816(acc[mt][nt], ah[mt], bl[nt]);
                    mma16816(acc[mt][nt], al[mt], bh[nt]);
                }
        }
        if (c + 1 < 16) {
            __nv_bfloat16* ns = smg + ((c + 1) & 1) * STG;
            *(uint4*)(ns + ar * BP + akb)            = rah;
            *(uint4*)(ns + ar * BP + akb + 8)        = rah2;
            *(uint4*)(ns + 5120 + ar * BP + akb)     = ral;
            *(uint4*)(ns + 5120 + ar * BP + akb + 8) = ral2;
            *(uint4*)(ns + 10240 + bkr * BPB + bnf)     = rbh;
            *(uint4*)(ns + 10240 + bkr * BPB + bnf + 8) = rbh2;
            *(uint4*)(ns + 14592 + bkr * BPB + bnf)     = rbl;
            *(uint4*)(ns + 14592 + bkr * BPB + bnf + 8) = rbl2;
            __syncthreads();
        }
    }

    const int part = cb >> 9;
    float* dst = part == 0 ? g_q : (part == 1 ? g_k : g_v);
    const float sc = part == 0 ? 0.125f : 1.f;
#pragma unroll
    for (int mt = 0; mt < 4; mt++) {
#pragma unroll
        for (int nt = 0; nt < 4; nt++) {
            int n = cb + wn * 32 + nt * 8 + (lane & 3) * 2;
            int hd = (n >> 6) & 7, d0 = n & 63;
#pragma unroll
            for (int half = 0; half < 2; half++) {
                int r = row0 + wm * 64 + mt * 16 + (lane >> 2) + half * 8;
                int b = r >> 14, i = r & (NN - 1);
                float* p = dst + ((size_t)(b * HH + hd) * NN + i) * DD + d0;
                *(float2*)p = make_float2(acc[mt][nt][half * 2] * sc,
                                          acc[mt][nt][half * 2 + 1] * sc);
            }
        }
    }
}

// ========== output GEMM: double-buffered + bias + scatter ==========
__global__ __launch_bounds__(256, 1) void out_mma_kernel(
    const float* __restrict__ bo, const int* __restrict__ index,
    float* __restrict__ out) {
    extern __shared__ __nv_bfloat16 smg[];
    const int tid = threadIdx.x, lane = tid & 31, wid = tid >> 5;
    const int wm = wid & 1, wn = wid >> 1;
    const int cb = blockIdx.x * 128, row0 = blockIdx.y * 128;

    const int ar = tid >> 1, akb = (tid & 1) << 4;
    const int bkr = tid & 31, bnf = (tid >> 5) << 4;
    const __nv_bfloat16* gah = g_oh + (size_t)(row0 + ar) * DIMM + akb;
    const __nv_bfloat16* gal = g_ol + (size_t)(row0 + ar) * DIMM + akb;
    const __nv_bfloat16* gbh = g_woh + (size_t)bkr * DIMM + cb + bnf;
    const __nv_bfloat16* gbl = g_wol + (size_t)bkr * DIMM + cb + bnf;

    float acc[4][4][4] = {};

    uint4 rah, rah2, ral, ral2, rbh, rbh2, rbl, rbl2;
    rah  = *(const uint4*)(gah);
    rah2 = *(const uint4*)(gah + 8);
    ral  = *(const uint4*)(gal);
    ral2 = *(const uint4*)(gal + 8);
    rbh  = *(const uint4*)(gbh);
    rbh2 = *(const uint4*)(gbh + 8);
    rbl  = *(const uint4*)(gbl);
    rbl2 = *(const uint4*)(gbl + 8);
    {
        __nv_bfloat16* bs = smg;
        *(uint4*)(bs + ar * BP + akb)            = rah;
        *(uint4*)(bs + ar * BP + akb + 8)        = rah2;
        *(uint4*)(bs + 5120 + ar * BP + akb)     = ral;
        *(uint4*)(bs + 5120 + ar * BP + akb + 8) = ral2;
        *(uint4*)(bs + 10240 + bkr * BPB + bnf)     = rbh;
        *(uint4*)(bs + 10240 + bkr * BPB + bnf + 8) = rbh2;
        *(uint4*)(bs + 14592 + bkr * BPB + bnf)     = rbl;
        *(uint4*)(bs + 14592 + bkr * BPB + bnf + 8) = rbl2;
    }
    __syncthreads();

    for (int c = 0; c < 16; c++) {
        if (c + 1 < 16) {
            const int k0 = (c + 1) * 32;
            rah  = *(const uint4*)(gah + k0);
            rah2 = *(const uint4*)(gah + k0 + 8);
            ral  = *(const uint4*)(gal + k0);
            ral2 = *(const uint4*)(gal + k0 + 8);
            rbh  = *(const uint4*)(gbh + (size_t)k0 * DIMM);
            rbh2 = *(const uint4*)(gbh + (size_t)k0 * DIMM + 8);
            rbl  = *(const uint4*)(gbl + (size_t)k0 * DIMM);
            rbl2 = *(const uint4*)(gbl + (size_t)k0 * DIMM + 8);
        }
        __nv_bfloat16* bs = smg + (c & 1) * STG;
#pragma unroll
        for (int ks = 0; ks < 2; ks++) {
            uint32_t ah[4][4], al[4][4], bh[4][2], bl[4][2];
            const int acol = ks * 16 + ((lane >> 4) << 3);
            const int krow = ks * 16 + (lane & 15);
#pragma unroll
            for (int mt = 0; mt < 4; mt++) {
                int arw = wm * 64 + mt * 16 + (lane & 15);
                ldmx4(ah[mt], (uint32_t)__cvta_generic_to_shared(bs + arw * BP + acol));
                ldmx4(al[mt], (uint32_t)__cvta_generic_to_shared(bs + 5120 + arw * BP + acol));
            }
#pragma unroll
            for (int nt = 0; nt < 4; nt++) {
                int n0 = wn * 32 + nt * 8;
                ldmx2t(bh[nt], (uint32_t)__cvta_generic_to_shared(bs + 10240 + krow * BPB + n0));
                ldmx2t(bl[nt], (uint32_t)__cvta_generic_to_shared(bs + 14592 + krow * BPB + n0));
            }
#pragma unroll
            for (int mt = 0; mt < 4; mt++)
#pragma unroll
                for (int nt = 0; nt < 4; nt++) {
                    mma16816(acc[mt][nt], ah[mt], bh[nt]);
                    mma16816(acc[mt][nt], ah[mt], bl[nt]);
                    mma16816(acc[mt][nt], al[mt], bh[nt]);
                }
        }
        if (c + 1 < 16) {
            __nv_bfloat16* ns = smg + ((c + 1) & 1) * STG;
            *(uint4*)(ns + ar * BP + akb)            = rah;
            *(uint4*)(ns + ar * BP + akb + 8)        = rah2;
            *(uint4*)(ns + 5120 + ar * BP + akb)     = ral;
            *(uint4*)(ns + 5120 + ar * BP + akb + 8) = ral2;
            *(uint4*)(ns + 10240 + bkr * BPB + bnf)     = rbh;
            *(uint4*)(ns + 10240 + bkr * BPB + bnf + 8) = rbh2;
            *(uint4*)(ns + 14592 + bkr * BPB + bnf)     = rbl;
            *(uint4*)(ns + 14592 + bkr * BPB + bnf + 8) = rbl2;
            __syncthreads();
        }
    }

#pragma unroll
    for (int mt = 0; mt < 4; mt++) {
#pragma unroll
        for (int nt = 0; nt < 4; nt++) {
            int n = cb + wn * 32 + nt * 8 + (lane & 3) * 2;
            float b0 = bo[n], b1 = bo[n + 1];
#pragma unroll
            for (int half = 0; half < 2; half++) {
                int r = row0 + wm * 64 + mt * 16 + (lane >> 2) + half * 8;
                int b = r >> 14, i = r & (NN - 1);
                int orow = b * NN + index[i];
                *(float2*)(out + (size_t)orow * DIMM + n) =
                    make_float2(acc[mt][nt][half * 2] + b0, acc[mt][nt][half * 2 + 1] + b1);
            }
        }
    }
}

// ------------------ landmarks: 4-way row-parallel segment means -------------
__global__ __launch_bounds__(256) void landmarks_kernel() {
    __shared__ float rq[4][64], rk[4][64];
    int j = blockIdx.x, bh = blockIdx.y;
    int d = threadIdx.x & 63, g = threadIdx.x >> 6;
    int s = g_segoff[j], e = g_segoff[j + 1];
    const float* qb = g_q + (size_t)bh * NN * DD;
    const float* kb = g_k + (size_t)bh * NN * DD;
    float sq = 0.f, sk = 0.f;
    for (int i = s + g; i < e; i += 4) {
        sq += qb[(size_t)i * DD + d];
        sk += kb[(size_t)i * DD + d];
    }
    rq[g][d] = sq; rk[g][d] = sk;
    __syncthreads();
    if (g == 0) {
        float tq = rq[0][d] + rq[1][d] + rq[2][d] + rq[3][d];
        float tk = rk[0][d] + rk[1][d] + rk[2][d] + rk[3][d];
        g_ql[((size_t)bh * LL + j) * DD + d] = tq * (1.0f / 64.0f);
        g_kl[((size_t)bh * LL + j) * DD + d] = tk * (1.0f / 64.0f);
    }
}

// ------------------ attn2 = softmax(q_l k_l^T) ------------------
__global__ __launch_bounds__(256) void attn2_kernel() {
    __shared__ float skl[LL * DD];
    __shared__ float ss[LL * 66];
    int bh = blockIdx.x, tid = threadIdx.x;
    for (int e = tid; e < LL * DD; e += 256) skl[e] = g_kl[(size_t)bh * LL * DD + e];
    __syncthreads();
    const float* qb = g_ql + (size_t)bh * LL * DD;
    for (int e = tid; e < LL * LL; e += 256) {
        int i = e / LL, j = e - i * LL;
        float s = 0.f;
        for (int d = 0; d < DD; d += 4) {
            float4 a = *(const float4*)(qb + i * DD + d);
            float4 b = *(float4*)&skl[j * DD + d];
            s += a.x * b.x + a.y * b.y + a.z * b.z + a.w * b.w;
        }
        ss[i * 66 + j] = s;
    }
    __syncthreads();
    int warp = tid >> 5, lane = tid & 31;
    for (int r = warp; r < LL; r += 8) {
        float mx = -1e30f;
        for (int j = lane; j < LL; j += 32) mx = fmaxf(mx, ss[r * 66 + j]);
        for (int o = 16; o; o >>= 1) mx = fmaxf(mx, __shfl_xor_sync(~0u, mx, o));
        float sum = 0.f;
        for (int j = lane; j < LL; j += 32) {
            float p = expf(ss[r * 66 + j] - mx);
            ss[r * 66 + j] = p; sum += p;
        }
        for (int o = 16; o; o >>= 1) sum += __shfl_xor_sync(~0u, sum, o);
        float inv = 1.f / sum;
        for (int j = lane; j < LL; j += 32)
            g_attn2[((size_t)bh * LL + r) * LL + j] = ss[r * 66 + j] * inv;
    }
}

// ------------------ global scalar ------------------
__global__ __launch_bounds__(256) void scal_kernel() {
    __shared__ float redc[256], redr[256];
    int tid = threadIdx.x;
    float mc = 0.f, mr = 0.f;
    for (int e = tid; e < BHH * LL; e += 256) {
        int bh = e / LL, i = e - bh * LL;
        const float* Xb = g_attn2 + (size_t)bh * LL * LL;
        float rs = 0.f, cs = 0.f;
        for (int j = 0; j < LL; j++) {
            rs += fabsf(Xb[i * LL + j]);
            cs += fabsf(Xb[j * LL + i]);
        }
        mc = fmaxf(mc, rs); mr = fmaxf(mr, cs);
    }
    redc[tid] = mc; redr[tid] = mr;
    __syncthreads();
    for (int s = 128; s > 0; s >>= 1) {
        if (tid < s) {
            redc[tid] = fmaxf(redc[tid], redc[tid + s]);
            redr[tid] = fmaxf(redr[tid], redr[tid + s]);
        }
        __syncthreads();
    }
    if (tid == 0) g_scal[0] = redc[0] * redr[0];
}

// ------------------ Moore-Penrose pinv ------------------
__device__ __forceinline__ void smm65(const float* __restrict__ P,
                                      const float* __restrict__ Q,
                                      float* __restrict__ O,
                                      float beta, float sgn, int tid) {
    for (int t = tid; t < 17 * 17; t += 256) {
        int tr = (t / 17) * 4, tc = (t % 17) * 4;
        float c[4][4] = {};
        for (int k = 0; k < LL; k++) {
            float a[4], b[4];
#pragma unroll
            for (int u = 0; u < 4; u++) { a[u] = P[(tr + u) * 68 + k]; b[u] = Q[k * 68 + tc + u]; }
#pragma unroll
            for (int u = 0; u < 4; u++)
#pragma unroll
                for (int v = 0; v < 4; v++) c[u][v] += a[u] * b[v];
        }
#pragma unroll
        for (int u = 0; u < 4; u++) {
            int i = tr + u; if (i >= LL) continue;
#pragma unroll
            for (int v = 0; v < 4; v++) {
                int j = tc + v; if (j >= LL) continue;
                O[i * 68 + j] = beta * P[i * 68 + j] + sgn * c[u][v];
            }
        }
    }
}

#define PMS (68 * 68)
#define PINV_SMEM (5 * PMS * 4)
__global__ __launch_bounds__(256) void pinv_kernel() {
    extern __shared__ float sm[];
    float* X = sm; float* Z = sm + PMS; float* A_ = sm + 2 * PMS;
    float* Bf = sm + 3 * PMS; float* Cf = sm + 4 * PMS;
    int bh = blockIdx.x, tid = threadIdx.x;
    for (int e = tid; e < 5 * PMS; e += 256) sm[e] = 0.f;
    __syncthreads();
    const float* Xg = g_attn2 + (size_t)bh * LL * LL;
    for (int e = tid; e < LL * LL; e += 256) {
        int i = e / LL, j = e - i * LL;
        X[i * 68 + j] = Xg[e];
    }
    __syncthreads();
    float inva = 1.0f / g_scal[0];
    for (int e = tid; e < LL * LL; e += 256) {
        int i = e / LL, j = e - i * LL;
        Z[i * 68 + j] = X[j * 68 + i] * inva;
    }
    __syncthreads();
    for (int it = 0; it < 6; it++) {
        smm65(X, Z, A_, 0.f, 1.f, tid);  __syncthreads();
        smm65(A_, A_, Bf, 7.f, -1.f, tid); __syncthreads();
        smm65(A_, Bf, Cf, 15.f, -1.f, tid); __syncthreads();
        smm65(Z, Cf, A_, 13.f, -1.f, tid); __syncthreads();
        for (int e = tid; e < LL * LL; e += 256) {
            int i = e / LL, j = e - i * LL;
            Z[i * 68 + j] = 0.25f * A_[i * 68 + j];
        }
        __syncthreads();
    }
    for (int e = tid; e < LL * LL; e += 256) {
        int i = e / LL, j = e - i * LL;
        g_z[(size_t)bh * LL * LL + e] = Z[i * 68 + j];
    }
}

// ------------------ split flash pass (strided rows: conflict-free) ----------
#define SPLIT_SMEM ((LL*68 + 64*68 + 64*DD + LL*DD + LL*66 + 3*LL) * 4)
__global__ __launch_bounds__(256) void split_kernel() {
    extern __shared__ float sm[];
    float* sQ = sm;
    float* sK = sQ + LL * 68;
    float* sV = sK + 64 * 68;
    float* accm = sV + 64 * DD;
    float* sS = accm + LL * DD;
    float* mrow = sS + LL * 66;
    float* lrow = mrow + LL;
    float* frow = lrow + LL;
    int sp = blockIdx.x, bh = blockIdx.y, tid = threadIdx.x;
    const float* Kb = g_k + (size_t)bh * NN * DD;
    const float* Vb = g_v + (size_t)bh * NN * DD;
    const float* Qg = g_ql + (size_t)bh * LL * DD;
    for (int e = tid; e < LL * 16; e += 256) {
        int r = e >> 4, c = (e & 15) << 2;
        *(float4*)&sQ[r * 68 + c] = *(const float4*)(Qg + r * DD + c);
    }
    for (int e = tid; e < LL * DD; e += 256) accm[e] = 0.f;
    if (tid < LL) { mrow[tid] = -1e30f; lrow[tid] = 0.f; }
    __syncthreads();
    int warp = tid >> 5, lane = tid & 31;
    for (int t = 0; t < CHUNK / 64; t++) {
        int i0 = sp * CHUNK + t * 64;
        for (int e = tid; e < 64 * 16; e += 256) {
            int r = e >> 4, c = (e & 15) << 2;
            *(float4*)&sK[r * 68 + c] = *(const float4*)(Kb + (size_t)(i0 + r) * DD + c);
            *(float4*)&sV[r * DD + c] = *(const float4*)(Vb + (size_t)(i0 + r) * DD + c);
        }
        __syncthreads();
        // scores: rows strided by 16 -> lane stride 1 row = 272 B (conflict-free)
        for (int e = tid; e < LL * 16; e += 256) {
            int r = e >> 4, ib = e & 15;
            float s0 = 0.f, s1 = 0.f, s2 = 0.f, s3 = 0.f;
            for (int d = 0; d < DD; d += 4) {
                float4 a = *(float4*)&sQ[r * 68 + d];
                float4 b0 = *(float4*)&sK[(ib + 0)  * 68 + d];
                float4 b1 = *(float4*)&sK[(ib + 16) * 68 + d];
                float4 b2 = *(float4*)&sK[(ib + 32) * 68 + d];
                float4 b3 = *(float4*)&sK[(ib + 48) * 68 + d];
                s0 += a.x * b0.x + a.y * b0.y + a.z * b0.z + a.w * b0.w;
                s1 += a.x * b1.x + a.y * b1.y + a.z * b1.z + a.w * b1.w;
                s2 += a.x * b2.x + a.y * b2.y + a.z * b2.z + a.w * b2.w;
                s3 += a.x * b3.x + a.y * b3.y + a.z * b3.z + a.w * b3.w;
            }
            sS[r * 66 + ib + 0]  = s0;
            sS[r * 66 + ib + 16] = s1;
            sS[r * 66 + ib + 32] = s2;
            sS[r * 66 + ib + 48] = s3;
        }
        __syncthreads();
        for (int r = warp; r < LL; r += 8) {
            float mx = -1e30f;
            for (int i = lane; i < 64; i += 32) mx = fmaxf(mx, sS[r * 66 + i]);
            for (int o = 16; o; o >>= 1) mx = fmaxf(mx, __shfl_xor_sync(~0u, mx, o));
            float mnew = fmaxf(mrow[r], mx);
            float sum = 0.f;
            for (int i = lane; i < 64; i += 32) {
                float p = expf(sS[r * 66 + i] - mnew);
                sS[r * 66 + i] = p; sum += p;
            }
            for (int o = 16; o; o >>= 1) sum += __shfl_xor_sync(~0u, sum, o);
            if (lane == 0) {
                float f = expf(mrow[r] - mnew);
                frow[r] = f;
                lrow[r] = lrow[r] * f + sum;
                mrow[r] = mnew;
            }
        }
        __syncthreads();
        {
            int r = tid >> 4, c = (tid & 15) << 2;
            int r2 = r + 32, r3 = r + 16, r4 = r + 48;
            float f1 = frow[r], f2 = frow[r2], f3 = frow[r3], f4 = frow[r4];
            float4 a1 = *(float4*)&accm[r * DD + c];
            float4 a2 = *(float4*)&accm[r2 * DD + c];
            float4 a3 = *(float4*)&accm[r3 * DD + c];
            float4 a4 = *(float4*)&accm[r4 * DD + c];
            a1.x *= f1; a1.y *= f1; a1.z *= f1; a1.w *= f1;
            a2.x *= f2; a2.y *= f2; a2.z *= f2; a2.w *= f2;
            a3.x *= f3; a3.y *= f3; a3.z *= f3; a3.w *= f3;
            a4.x *= f4; a4.y *= f4; a4.z *= f4; a4.w *= f4;
            for (int i = 0; i < 64; i++) {
                float4 vv = *(float4*)&sV[i * DD + c];
                float p1 = sS[r * 66 + i], p2 = sS[r2 * 66 + i];
                float p3 = sS[r3 * 66 + i], p4 = sS[r4 * 66 + i];
                a1.x += p1 * vv.x; a1.y += p1 * vv.y; a1.z += p1 * vv.z; a1.w += p1 * vv.w;
                a2.x += p2 * vv.x; a2.y += p2 * vv.y; a2.z += p2 * vv.z; a2.w += p2 * vv.w;
                a3.x += p3 * vv.x; a3.y += p3 * vv.y; a3.z += p3 * vv.z; a3.w += p3 * vv.w;
                a4.x += p4 * vv.x; a4.y += p4 * vv.y; a4.z += p4 * vv.z; a4.w += p4 * vv.w;
            }
            *(float4*)&accm[r * DD + c] = a1;
            *(float4*)&accm[r2 * DD + c] = a2;
            *(float4*)&accm[r3 * DD + c] = a3;
            *(float4*)&accm[r4 * DD + c] = a4;
        }
        if (tid < 16) {
            int c = tid << 2;
            float f = frow[64];
            float4 a = *(float4*)&accm[64 * DD + c];
            a.x *= f; a.y *= f; a.z *= f; a.w *= f;
            for (int i = 0; i < 64; i++) {
                float p = sS[64 * 66 + i];
                float4 vv = *(float4*)&sV[i * DD + c];
                a.x += p * vv.x; a.y += p * vv.y; a.z += p * vv.z; a.w += p * vv.w;
            }
            *(float4*)&accm[64 * DD + c] = a;
        }
        __syncthreads();
    }
    size_t pb = (size_t)(bh * NSPLIT + sp);
    for (int e = tid; e < LL * DD; e += 256) g_pacc[pb * LL * DD + e] = accm[e];
    if (tid < LL) { g_pm[pb * LL + tid] = mrow[tid]; g_pl[pb * LL + tid] = lrow[tid]; }
}

// ------------------ combine ------------------
__global__ void combine_kernel() {
    int j = blockIdx.x, bh = blockIdx.y, d = threadIdx.x;
    float M = -1e30f;
    for (int s = 0; s < NSPLIT; s++)
        M = fmaxf(M, g_pm[((size_t)(bh * NSPLIT + s)) * LL + j]);
    float lsum = 0.f, a = 0.f;
    for (int s = 0; s < NSPLIT; s++) {
        size_t pb = (size_t)(bh * NSPLIT + s);
        float w = expf(g_pm[pb * LL + j] - M);
        lsum += w * g_pl[pb * LL + j];
        a += w * g_pacc[(pb * LL + j) * DD + d];
    }
    g_tmp1[((size_t)bh * LL + j) * DD + d] = a / lsum;
}

// ------------------ tmp2 = z @ tmp1 ------------------
__global__ __launch_bounds__(256) void tmp2_kernel() {
    __shared__ float sT[LL * DD];
    __shared__ float sZ[LL * 68];
    int bh = blockIdx.x, tid = threadIdx.x;
    for (int e = tid; e < LL * DD; e += 256) sT[e] = g_tmp1[(size_t)bh * LL * DD + e];
    for (int e = tid; e < LL * LL; e += 256) {
        int i = e / LL, j = e - i * LL;
        sZ[i * 68 + j] = g_z[(size_t)bh * LL * LL + e];
    }
    __syncthreads();
    for (int e = tid; e < LL * 16; e += 256) {
        int j = e >> 4, c = (e & 15) << 2;
        float4 acc = make_float4(0.f, 0.f, 0.f, 0.f);
        for (int m = 0; m < LL; m++) {
            float z = sZ[j * 68 + m];
            float4 t = *(float4*)&sT[m * DD + c];
            acc.x += z * t.x; acc.y += z * t.y; acc.z += z * t.z; acc.w += z * t.w;
        }
        *(float4*)(g_tmp2 + (size_t)bh * LL * DD + j * DD + c) = acc;
    }
}

// ------------------ fused final: strided rows, emits bf16 hi/lo -------------
#define FINAL_SMEM ((68*68 + LL*68 + 32*68 + 64*DD + 32*66 + 36 + 32) * 4)
__global__ __launch_bounds__(256) void final_kernel(const float* __restrict__ wres) {
    extern __shared__ float sm[];
    float* sKL = sm;
    float* sT2 = sKL + 68 * 68;
    float* sQ2 = sT2 + LL * 68;
    float* sVs = sQ2 + 32 * 68;
    float* sS  = sVs + 64 * DD;
    float* sw  = sS + 32 * 66;
    float* sinv = sw + 36;
    int it = blockIdx.x, bh = blockIdx.y, tid = threadIdx.x;
    int hd = bh & 7, b = bh >> 3;
    int i0 = it * 32;
    const float* KLg = g_kl + (size_t)bh * LL * DD;
    const float* T2g = g_tmp2 + (size_t)bh * LL * DD;
    for (int e = tid; e < LL * 16; e += 256) {
        int r = e >> 4, c = (e & 15) << 2;
        *(float4*)&sKL[r * 68 + c] = *(const float4*)(KLg + r * DD + c);
        *(float4*)&sT2[r * 68 + c] = *(const float4*)(T2g + r * DD + c);
    }
    for (int e = tid; e < 3 * 68; e += 256) sKL[65 * 68 + e] = 0.f;
    for (int e = tid; e < 32 * 16; e += 256) {
        int r = e >> 4, c = (e & 15) << 2;
        *(float4*)&sQ2[r * 68 + c] =
            *(const float4*)(g_q + ((size_t)bh * NN + i0 + r) * DD + c);
    }
    for (int e = tid; e < 64 * 16; e += 256) {
        int r = e >> 4, c = (e & 15) << 2;
        int gi = i0 - 16 + r;
        float4 vv = make_float4(0.f, 0.f, 0.f, 0.f);
        if (gi >= 0 && gi < NN) vv = *(const float4*)(g_v + ((size_t)bh * NN + gi) * DD + c);
        *(float4*)&sVs[r * DD + c] = vv;
    }
    if (tid < 33) sw[tid] = wres[hd * 33 + tid];
    __syncthreads();
    // scores: rows strided by 17 -> lane stride 1 row (conflict-free); pad rows zero
    for (int e = tid; e < 32 * 17; e += 256) {
        int r = e / 17, jb = e - r * 17;
        float s0 = 0.f, s1 = 0.f, s2 = 0.f, s3 = 0.f;
        for (int d = 0; d < DD; d += 4) {
            float4 a = *(float4*)&sQ2[r * 68 + d];
            float4 b0 = *(float4*)&sKL[(jb + 0)  * 68 + d];
            float4 b1 = *(float4*)&sKL[(jb + 17) * 68 + d];
            float4 b2 = *(float4*)&sKL[(jb + 34) * 68 + d];
            float4 b3 = *(float4*)&sKL[(jb + 51) * 68 + d];
            s0 += a.x * b0.x + a.y * b0.y + a.z * b0.z + a.w * b0.w;
            s1 += a.x * b1.x + a.y * b1.y + a.z * b1.z + a.w * b1.w;
            s2 += a.x * b2.x + a.y * b2.y + a.z * b2.z + a.w * b2.w;
            s3 += a.x * b3.x + a.y * b3.y + a.z * b3.z + a.w * b3.w;
        }
        sS[r * 66 + jb + 0]  = s0;
        sS[r * 66 + jb + 17] = s1;
        sS[r * 66 + jb + 34] = s2;
        if (jb + 51 <= 64) sS[r * 66 + jb + 51] = s3;
    }
    __syncthreads();
    int warp = tid >> 5, lane = tid & 31;
    for (int r = warp; r < 32; r += 8) {
        float mx = -1e30f;
        for (int j = lane; j < LL; j += 32) mx = fmaxf(mx, sS[r * 66 + j]);
        for (int o = 16; o; o >>= 1) mx = fmaxf(mx, __shfl_xor_sync(~0u, mx, o));
        float sum = 0.f;
        for (int j = lane; j < LL; j += 32) {
            float p = expf(sS[r * 66 + j] - mx);
            sS[r * 66 + j] = p; sum += p;
        }
        for (int o = 16; o; o >>= 1) sum += __shfl_xor_sync(~0u, sum, o);
        if (lane == 0) sinv[r] = 1.f / sum;
    }
    __syncthreads();
    {
        int r = tid >> 4, c = (tid & 15) << 2;
        int r2 = r + 16;
        float4 a1 = make_float4(0.f, 0.f, 0.f, 0.f);
        float4 a2 = make_float4(0.f, 0.f, 0.f, 0.f);
        for (int j = 0; j < LL; j++) {
            float4 t = *(float4*)&sT2[j * 68 + c];
            float p1 = sS[r * 66 + j], p2 = sS[r2 * 66 + j];
            a1.x += p1 * t.x; a1.y += p1 * t.y; a1.z += p1 * t.z; a1.w += p1 * t.w;
            a2.x += p2 * t.x; a2.y += p2 * t.y; a2.z += p2 * t.z; a2.w += p2 * t.w;
        }
        float i1 = sinv[r], i2 = sinv[r2];
        a1.x *= i1; a1.y *= i1; a1.z *= i1; a1.w *= i1;
        a2.x *= i2; a2.y *= i2; a2.z *= i2; a2.w *= i2;
        for (int k = 0; k < 33; k++) {
            float wv = sw[k];
            float4 v1 = *(float4*)&sVs[(r + k) * DD + c];
            float4 v2 = *(float4*)&sVs[(r2 + k) * DD + c];
            a1.x += wv * v1.x; a1.y += wv * v1.y; a1.z += wv * v1.z; a1.w += wv * v1.w;
            a2.x += wv * v2.x; a2.y += wv * v2.y; a2.z += wv * v2.z; a2.w += wv * v2.w;
        }
        __nv_bfloat16 h0, h1, h2, h3, l0, l1, l2, l3;
        size_t off1 = ((size_t)b * NN + i0 + r) * DIMM + hd * DD + c;
        size_t off2 = ((size_t)b * NN + i0 + r2) * DIMM + hd * DD + c;
        bf_split(a1.x, h0, l0); bf_split(a1.y, h1, l1);
        bf_split(a1.z, h2, l2); bf_split(a1.w, h3, l3);
        *(uint2*)(g_oh + off1) = make_uint2(pack2(h0, h1), pack2(h2, h3));
        *(uint2*)(g_ol + off1) = make_uint2(pack2(l0, l1), pack2(l2, l3));
        bf_split(a2.x, h0, l0); bf_split(a2.y, h1, l1);
        bf_split(a2.z, h2, l2); bf_split(a2.w, h3, l3);
        *(uint2*)(g_oh + off2) = make_uint2(pack2(h0, h1), pack2(h2, h3));
        *(uint2*)(g_ol + off2) = make_uint2(pack2(l0, l1), pack2(l2, l3));
    }
}

// ------------------ launch ------------------
extern "C" void kernel_launch(void* const* d_in, const int* in_sizes, int n_in,
                              void* d_out, int out_size) {
    const float* x     = (const float*)d_in[0];
    const int*   index = (const int*)d_in[1];
    const int*   seg   = (const int*)d_in[3];
    const float* wqkv  = (const float*)d_in[4];
    const float* wout  = (const float*)d_in[5];
    const float* bout  = (const float*)d_in[6];
    const float* wres  = (const float*)d_in[7];
    float* out = (float*)d_out;

    __nv_bfloat16 *p_wqh, *p_wql, *p_woh, *p_wol;
    cudaGetSymbolAddress((void**)&p_wqh, g_wqh);
    cudaGetSymbolAddress((void**)&p_wql, g_wql);
    cudaGetSymbolAddress((void**)&p_woh, g_woh);
    cudaGetSymbolAddress((void**)&p_wol, g_wol);

    cudaFuncSetAttribute(pinv_kernel,  cudaFuncAttributeMaxDynamicSharedMemorySize, PINV_SMEM);
    cudaFuncSetAttribute(split_kernel, cudaFuncAttributeMaxDynamicSharedMemorySize, SPLIT_SMEM);
    cudaFuncSetAttribute(final_kernel, cudaFuncAttributeMaxDynamicSharedMemorySize, FINAL_SMEM);
    cudaFuncSetAttribute(qkv_mma_kernel, cudaFuncAttributeMaxDynamicSharedMemorySize, GEMM_SMEM);
    cudaFuncSetAttribute(out_mma_kernel, cudaFuncAttributeMaxDynamicSharedMemorySize, GEMM_SMEM);

    seg_init_kernel<<<1, 128>>>();
    seg_count_kernel<<<64, 256>>>(seg);
    seg_scan_kernel<<<1, 32>>>();
    conv_x_kernel<<<8192, 256>>>(x, index);
    conv_w_kernel<<<384, 256>>>(wqkv, p_wqh, p_wql);
    conv_w_kernel<<<128, 256>>>(wout, p_woh, p_wol);
    qkv_mma_kernel<<<dim3(12, 256), 256, GEMM_SMEM>>>();
    landmarks_kernel<<<dim3(LL, BHH), 256>>>();
    attn2_kernel<<<BHH, 256>>>();
    scal_kernel<<<1, 256>>>();
    pinv_kernel<<<BHH, 256, PINV_SMEM>>>();
    split_kernel<<<dim3(NSPLIT, BHH), 256, SPLIT_SMEM>>>();
    combine_kernel<<<dim3(LL, BHH), 64>>>();
    tmp2_kernel<<<BHH, 256>>>();
    final_kernel<<<dim3(NN / 32, BHH), 256, FINAL_SMEM>>>(wres);
    out_mma_kernel<<<dim3(4, 256), 256, GEMM_SMEM>>>(bout, index, out);
}

// round 16
// speedup vs baseline: 1.5430x; 1.0089x over previous
#include <cuda_runtime.h>
#include <cuda_bf16.h>
#include <cstdint>
#include <math.h>

#define NN 16384
#define HH 8
#define DD 64
#define LL 65
#define BHH 16
#define NSPLIT 16
#define CHUNK 1024
#define DIMM 512
#define QKVN 1536

// ------------------ device scratch (allocation-free rule) -------------------
__device__ float g_q[(size_t)BHH * NN * DD];
__device__ float g_k[(size_t)BHH * NN * DD];
__device__ float g_v[(size_t)BHH * NN * DD];
__device__ float g_ql[BHH * LL * DD];
__device__ float g_kl[BHH * LL * DD];
__device__ float g_attn2[BHH * LL * LL];
__device__ float g_z[BHH * LL * LL];
__device__ float g_scal[1];
__device__ float g_pm[BHH * NSPLIT * LL];
__device__ float g_pl[BHH * NSPLIT * LL];
__device__ float g_pacc[BHH * NSPLIT * LL * DD];
__device__ float g_tmp1[BHH * LL * DD];
__device__ float g_tmp2[BHH * LL * DD];
__device__ int   g_segcnt[LL];
__device__ int   g_segoff[LL + 1];
// bf16 hi/lo staging
__device__ __nv_bfloat16 g_xqh[(size_t)2 * NN * DIMM];
__device__ __nv_bfloat16 g_xql[(size_t)2 * NN * DIMM];
__device__ __nv_bfloat16 g_wqh[DIMM * QKVN];
__device__ __nv_bfloat16 g_wql[DIMM * QKVN];
__device__ __nv_bfloat16 g_oh[(size_t)2 * NN * DIMM];
__device__ __nv_bfloat16 g_ol[(size_t)2 * NN * DIMM];
__device__ __nv_bfloat16 g_woh[DIMM * DIMM];
__device__ __nv_bfloat16 g_wol[DIMM * DIMM];

// ================== mma.sync helpers =========
__device__ __forceinline__ void mma16816(float* c, const uint32_t* a, const uint32_t* b) {
    asm volatile(
        "mma.sync.aligned.m16n8k16.row.col.f32.bf16.bf16.f32 "
        "{%0,%1,%2,%3}, {%4,%5,%6,%7}, {%8,%9}, {%0,%1,%2,%3};"
        : "+f"(c[0]), "+f"(c[1]), "+f"(c[2]), "+f"(c[3])
        : "r"(a[0]), "r"(a[1]), "r"(a[2]), "r"(a[3]), "r"(b[0]), "r"(b[1]));
}
__device__ __forceinline__ void ldmx4(uint32_t* r, uint32_t addr) {
    asm volatile("ldmatrix.sync.aligned.m8n8.x4.shared.b16 {%0,%1,%2,%3}, [%4];"
                 : "=r"(r[0]), "=r"(r[1]), "=r"(r[2]), "=r"(r[3]) : "r"(addr));
}
__device__ __forceinline__ void ldmx2t(uint32_t* r, uint32_t addr) {
    asm volatile("ldmatrix.sync.aligned.m8n8.x2.trans.shared.b16 {%0,%1}, [%2];"
                 : "=r"(r[0]), "=r"(r[1]) : "r"(addr));
}
__device__ __forceinline__ void bf_split(float v, __nv_bfloat16& h, __nv_bfloat16& l) {
    h = __float2bfloat16(v);
    l = __float2bfloat16(v - __bfloat162float(h));
}
__device__ __forceinline__ uint32_t pack2(__nv_bfloat16 a, __nv_bfloat16 b) {
    return (uint32_t)__bfloat16_as_ushort(a) | ((uint32_t)__bfloat16_as_ushort(b) << 16);
}

#define BP 40    // A smem row pitch (bf16 elems)
#define BPB 136  // B smem row pitch (bf16 elems), k-major 32x136
#define STG 18944
#define EPI_P 132                       // fp32 staging pitch
#define GEMM_SMEM_MAIN (2 * STG * 2)
#define GEMM_SMEM_EPI  (128 * EPI_P * 4)
#define GEMM_SMEM (GEMM_SMEM_EPI > GEMM_SMEM_MAIN ? GEMM_SMEM_EPI : GEMM_SMEM_MAIN)

// ------------------ segment offsets ------------------
__global__ void seg_init_kernel() { if (threadIdx.x < LL) g_segcnt[threadIdx.x] = 0; }
__global__ void seg_count_kernel(const int* __restrict__ seg) {
    int i = blockIdx.x * 256 + threadIdx.x;
    if (i < NN) atomicAdd(&g_segcnt[seg[i]], 1);
}
__global__ void seg_scan_kernel() {
    if (threadIdx.x == 0) {
        int acc = 0;
        for (int j = 0; j < LL; j++) { g_segoff[j] = acc; acc += g_segcnt[j]; }
        g_segoff[LL] = acc;
    }
}

// ------------------ conversion kernels (union-free) ------------------
__global__ __launch_bounds__(256) void conv_x_kernel(
    const float* __restrict__ x, const int* __restrict__ index) {
    size_t idx = ((size_t)blockIdx.x * 256 + threadIdx.x) * 8;
    int r = (int)(idx >> 9), c = (int)(idx & 511);
    int b = r >> 14, i = r & (NN - 1);
    int ar = b * NN + index[i];
    const float* s = x + (size_t)ar * DIMM + c;
    float4 v0 = *(const float4*)s, v1 = *(const float4*)(s + 4);
    __nv_bfloat16 h0, h1, h2, h3, h4, h5, h6, h7;
    __nv_bfloat16 l0, l1, l2, l3, l4, l5, l6, l7;
    bf_split(v0.x, h0, l0); bf_split(v0.y, h1, l1);
    bf_split(v0.z, h2, l2); bf_split(v0.w, h3, l3);
    bf_split(v1.x, h4, l4); bf_split(v1.y, h5, l5);
    bf_split(v1.z, h6, l6); bf_split(v1.w, h7, l7);
    uint4 H = make_uint4(pack2(h0, h1), pack2(h2, h3), pack2(h4, h5), pack2(h6, h7));
    uint4 L = make_uint4(pack2(l0, l1), pack2(l2, l3), pack2(l4, l5), pack2(l6, l7));
    *(uint4*)(g_xqh + idx) = H;
    *(uint4*)(g_xql + idx) = L;
}
__global__ __launch_bounds__(256) void conv_w_kernel(
    const float* __restrict__ src, __nv_bfloat16* __restrict__ dh,
    __nv_bfloat16* __restrict__ dl) {
    size_t idx = ((size_t)blockIdx.x * 256 + threadIdx.x) * 8;
    float4 v0 = *(const float4*)(src + idx), v1 = *(const float4*)(src + idx + 4);
    __nv_bfloat16 h0, h1, h2, h3, h4, h5, h6, h7;
    __nv_bfloat16 l0, l1, l2, l3, l4, l5, l6, l7;
    bf_split(v0.x, h0, l0); bf_split(v0.y, h1, l1);
    bf_split(v0.z, h2, l2); bf_split(v0.w, h3, l3);
    bf_split(v1.x, h4, l4); bf_split(v1.y, h5, l5);
    bf_split(v1.z, h6, l6); bf_split(v1.w, h7, l7);
    uint4 H = make_uint4(pack2(h0, h1), pack2(h2, h3), pack2(h4, h5), pack2(h6, h7));
    uint4 L = make_uint4(pack2(l0, l1), pack2(l2, l3), pack2(l4, l5), pack2(l6, l7));
    *(uint4*)(dh + idx) = H;
    *(uint4*)(dl + idx) = L;
}

// ========== QKV GEMM: 128x128 tile, double-buffered smem, staged epilogue ===
__global__ __launch_bounds__(256, 1) void qkv_mma_kernel() {
    extern __shared__ __nv_bfloat16 smg[];
    const int tid = threadIdx.x, lane = tid & 31, wid = tid >> 5;
    const int wm = wid & 1, wn = wid >> 1;
    const int cb = blockIdx.x * 128, row0 = blockIdx.y * 128;

    const int ar = tid >> 1, akb = (tid & 1) << 4;
    const int bkr = tid & 31, bnf = (tid >> 5) << 4;
    const __nv_bfloat16* gah = g_xqh + (size_t)(row0 + ar) * DIMM + akb;
    const __nv_bfloat16* gal = g_xql + (size_t)(row0 + ar) * DIMM + akb;
    const __nv_bfloat16* gbh = g_wqh + (size_t)bkr * QKVN + cb + bnf;
    const __nv_bfloat16* gbl = g_wql + (size_t)bkr * QKVN + cb + bnf;

    float acc[4][4][4] = {};

    uint4 rah, rah2, ral, ral2, rbh, rbh2, rbl, rbl2;
    rah  = *(const uint4*)(gah);
    rah2 = *(const uint4*)(gah + 8);
    ral  = *(const uint4*)(gal);
    ral2 = *(const uint4*)(gal + 8);
    rbh  = *(const uint4*)(gbh);
    rbh2 = *(const uint4*)(gbh + 8);
    rbl  = *(const uint4*)(gbl);
    rbl2 = *(const uint4*)(gbl + 8);
    {
        __nv_bfloat16* bs = smg;
        *(uint4*)(bs + ar * BP + akb)            = rah;
        *(uint4*)(bs + ar * BP + akb + 8)        = rah2;
        *(uint4*)(bs + 5120 + ar * BP + akb)     = ral;
        *(uint4*)(bs + 5120 + ar * BP + akb + 8) = ral2;
        *(uint4*)(bs + 10240 + bkr * BPB + bnf)     = rbh;
        *(uint4*)(bs + 10240 + bkr * BPB + bnf + 8) = rbh2;
        *(uint4*)(bs + 14592 + bkr * BPB + bnf)     = rbl;
        *(uint4*)(bs + 14592 + bkr * BPB + bnf + 8) = rbl2;
    }
    __syncthreads();

    for (int c = 0; c < 16; c++) {
        if (c + 1 < 16) {
            const int k0 = (c + 1) * 32;
            rah  = *(const uint4*)(gah + k0);
            rah2 = *(const uint4*)(gah + k0 + 8);
            ral  = *(const uint4*)(gal + k0);
            ral2 = *(const uint4*)(gal + k0 + 8);
            rbh  = *(const uint4*)(gbh + (size_t)k0 * QKVN);
            rbh2 = *(const uint4*)(gbh + (size_t)k0 * QKVN + 8);
            rbl  = *(const uint4*)(gbl + (size_t)k0 * QKVN);
            rbl2 = *(const uint4*)(gbl + (size_t)k0 * QKVN + 8);
        }
        __nv_bfloat16* bs = smg + (c & 1) * STG;
#pragma unroll
        for (int ks = 0; ks < 2; ks++) {
            uint32_t ah[4][4], al[4][4], bh[4][2], bl[4][2];
            const int acol = ks * 16 + ((lane >> 4) << 3);
            const int krow = ks * 16 + (lane & 15);
#pragma unroll
            for (int mt = 0; mt < 4; mt++) {
                int arw = wm * 64 + mt * 16 + (lane & 15);
                ldmx4(ah[mt], (uint32_t)__cvta_generic_to_shared(bs + arw * BP + acol));
                ldmx4(al[mt], (uint32_t)__cvta_generic_to_shared(bs + 5120 + arw * BP + acol));
            }
#pragma unroll
            for (int nt = 0; nt < 4; nt++) {
                int n0 = wn * 32 + nt * 8;
                ldmx2t(bh[nt], (uint32_t)__cvta_generic_to_shared(bs + 10240 + krow * BPB + n0));
                ldmx2t(bl[nt], (uint32_t)__cvta_generic_to_shared(bs + 14592 + krow * BPB + n0));
            }
#pragma unroll
            for (int mt = 0; mt < 4; mt++)
#pragma unroll
                for (int nt = 0; nt < 4; nt++) {
                    mma16816(acc[mt][nt], ah[mt], bh[nt]);
                    mma16816(acc[mt][nt], ah[mt], bl[nt]);
                    mma16816(acc[mt][nt], al[mt], bh[nt]);
                }
        }
        if (c + 1 < 16) {
            __nv_bfloat16* ns = smg + ((c + 1) & 1) * STG;
            *(uint4*)(ns + ar * BP + akb)            = rah;
            *(uint4*)(ns + ar * BP + akb + 8)        = rah2;
            *(uint4*)(ns + 5120 + ar * BP + akb)     = ral;
            *(uint4*)(ns + 5120 + ar * BP + akb + 8) = ral2;
            *(uint4*)(ns + 10240 + bkr * BPB + bnf)     = rbh;
            *(uint4*)(ns + 10240 + bkr * BPB + bnf + 8) = rbh2;
            *(uint4*)(ns + 14592 + bkr * BPB + bnf)     = rbl;
            *(uint4*)(ns + 14592 + bkr * BPB + bnf + 8) = rbl2;
            __syncthreads();
        }
    }

    // staged epilogue: fragments -> smem (pitch 132) -> coalesced scatter
    __syncthreads();
    float* smf = (float*)smg;
    const int part = cb >> 9;
    const float sc = part == 0 ? 0.125f : 1.f;
#pragma unroll
    for (int mt = 0; mt < 4; mt++) {
#pragma unroll
        for (int nt = 0; nt < 4; nt++) {
            int cl = wn * 32 + nt * 8 + (lane & 3) * 2;
#pragma unroll
            for (int half = 0; half < 2; half++) {
                int rl = wm * 64 + mt * 16 + (lane >> 2) + half * 8;
                *(float2*)&smf[rl * EPI_P + cl] =
                    make_float2(acc[mt][nt][half * 2] * sc, acc[mt][nt][half * 2 + 1] * sc);
            }
        }
    }
    __syncthreads();
    float* dst = part == 0 ? g_q : (part == 1 ? g_k : g_v);
    const int hd0 = (cb >> 6) & 7;
    for (int e = tid; e < 128 * 32; e += 256) {
        int r = e >> 5, cg = (e & 31) << 2;
        int rr = row0 + r;
        int b = rr >> 14, i = rr & (NN - 1);
        int hd = hd0 + (cg >> 6);
        float4 v = *(float4*)&smf[r * EPI_P + cg];
        *(float4*)(dst + ((size_t)(b * HH + hd) * NN + i) * DD + (cg & 63)) = v;
    }
}

// ========== output GEMM: double-buffered + staged epilogue + bias + scatter =
__global__ __launch_bounds__(256, 1) void out_mma_kernel(
    const float* __restrict__ bo, const int* __restrict__ index,
    float* __restrict__ out) {
    extern __shared__ __nv_bfloat16 smg[];
    __shared__ int arow[128];
    const int tid = threadIdx.x, lane = tid & 31, wid = tid >> 5;
    const int wm = wid & 1, wn = wid >> 1;
    const int cb = blockIdx.x * 128, row0 = blockIdx.y * 128;

    if (tid < 128) {
        int rr = row0 + tid;
        int b = rr >> 14, i = rr & (NN - 1);
        arow[tid] = b * NN + index[i];
    }

    const int ar = tid >> 1, akb = (tid & 1) << 4;
    const int bkr = tid & 31, bnf = (tid >> 5) << 4;
    const __nv_bfloat16* gah = g_oh + (size_t)(row0 + ar) * DIMM + akb;
    const __nv_bfloat16* gal = g_ol + (size_t)(row0 + ar) * DIMM + akb;
    const __nv_bfloat16* gbh = g_woh + (size_t)bkr * DIMM + cb + bnf;
    const __nv_bfloat16* gbl = g_wol + (size_t)bkr * DIMM + cb + bnf;

    float acc[4][4][4] = {};

    uint4 rah, rah2, ral, ral2, rbh, rbh2, rbl, rbl2;
    rah  = *(const uint4*)(gah);
    rah2 = *(const uint4*)(gah + 8);
    ral  = *(const uint4*)(gal);
    ral2 = *(const uint4*)(gal + 8);
    rbh  = *(const uint4*)(gbh);
    rbh2 = *(const uint4*)(gbh + 8);
    rbl  = *(const uint4*)(gbl);
    rbl2 = *(const uint4*)(gbl + 8);
    {
        __nv_bfloat16* bs = smg;
        *(uint4*)(bs + ar * BP + akb)            = rah;
        *(uint4*)(bs + ar * BP + akb + 8)        = rah2;
        *(uint4*)(bs + 5120 + ar * BP + akb)     = ral;
        *(uint4*)(bs + 5120 + ar * BP + akb + 8) = ral2;
        *(uint4*)(bs + 10240 + bkr * BPB + bnf)     = rbh;
        *(uint4*)(bs + 10240 + bkr * BPB + bnf + 8) = rbh2;
        *(uint4*)(bs + 14592 + bkr * BPB + bnf)     = rbl;
        *(uint4*)(bs + 14592 + bkr * BPB + bnf + 8) = rbl2;
    }
    __syncthreads();

    for (int c = 0; c < 16; c++) {
        if (c + 1 < 16) {
            const int k0 = (c + 1) * 32;
            rah  = *(const uint4*)(gah + k0);
            rah2 = *(const uint4*)(gah + k0 + 8);
            ral  = *(const uint4*)(gal + k0);
            ral2 = *(const uint4*)(gal + k0 + 8);
            rbh  = *(const uint4*)(gbh + (size_t)k0 * DIMM);
            rbh2 = *(const uint4*)(gbh + (size_t)k0 * DIMM + 8);
            rbl  = *(const uint4*)(gbl + (size_t)k0 * DIMM);
            rbl2 = *(const uint4*)(gbl + (size_t)k0 * DIMM + 8);
        }
        __nv_bfloat16* bs = smg + (c & 1) * STG;
#pragma unroll
        for (int ks = 0; ks < 2; ks++) {
            uint32_t ah[4][4], al[4][4], bh[4][2], bl[4][2];
            const int acol = ks * 16 + ((lane >> 4) << 3);
            const int krow = ks * 16 + (lane & 15);
#pragma unroll
            for (int mt = 0; mt < 4; mt++) {
                int arw = wm * 64 + mt * 16 + (lane & 15);
                ldmx4(ah[mt], (uint32_t)__cvta_generic_to_shared(bs + arw * BP + acol));
                ldmx4(al[mt], (uint32_t)__cvta_generic_to_shared(bs + 5120 + arw * BP + acol));
            }
#pragma unroll
            for (int nt = 0; nt < 4; nt++) {
                int n0 = wn * 32 + nt * 8;
                ldmx2t(bh[nt], (uint32_t)__cvta_generic_to_shared(bs + 10240 + krow * BPB + n0));
                ldmx2t(bl[nt], (uint32_t)__cvta_generic_to_shared(bs + 14592 + krow * BPB + n0));
            }
#pragma unroll
            for (int mt = 0; mt < 4; mt++)
#pragma unroll
                for (int nt = 0; nt < 4; nt++) {
                    mma16816(acc[mt][nt], ah[mt], bh[nt]);
                    mma16816(acc[mt][nt], ah[mt], bl[nt]);
                    mma16816(acc[mt][nt], al[mt], bh[nt]);
                }
        }
        if (c + 1 < 16) {
            __nv_bfloat16* ns = smg + ((c + 1) & 1) * STG;
            *(uint4*)(ns + ar * BP + akb)            = rah;
            *(uint4*)(ns + ar * BP + akb + 8)        = rah2;
            *(uint4*)(ns + 5120 + ar * BP + akb)     = ral;
            *(uint4*)(ns + 5120 + ar * BP + akb + 8) = ral2;
            *(uint4*)(ns + 10240 + bkr * BPB + bnf)     = rbh;
            *(uint4*)(ns + 10240 + bkr * BPB + bnf + 8) = rbh2;
            *(uint4*)(ns + 14592 + bkr * BPB + bnf)     = rbl;
            *(uint4*)(ns + 14592 + bkr * BPB + bnf + 8) = rbl2;
            __syncthreads();
        }
    }

    __syncthreads();
    float* smf = (float*)smg;
#pragma unroll
    for (int mt = 0; mt < 4; mt++) {
#pragma unroll
        for (int nt = 0; nt < 4; nt++) {
            int cl = wn * 32 + nt * 8 + (lane & 3) * 2;
#pragma unroll
            for (int half = 0; half < 2; half++) {
                int rl = wm * 64 + mt * 16 + (lane >> 2) + half * 8;
                *(float2*)&smf[rl * EPI_P + cl] =
                    make_float2(acc[mt][nt][half * 2], acc[mt][nt][half * 2 + 1]);
            }
        }
    }
    __syncthreads();
    for (int e = tid; e < 128 * 32; e += 256) {
        int r = e >> 5, cg = (e & 31) << 2;
        float4 v = *(float4*)&smf[r * EPI_P + cg];
        float4 bi = *(const float4*)(bo + cb + cg);
        v.x += bi.x; v.y += bi.y; v.z += bi.z; v.w += bi.w;
        *(float4*)(out + (size_t)arow[r] * DIMM + cb + cg) = v;
    }
}

// ------------------ landmarks: 4-way row-parallel segment means -------------
__global__ __launch_bounds__(256) void landmarks_kernel() {
    __shared__ float rq[4][64], rk[4][64];
    int j = blockIdx.x, bh = blockIdx.y;
    int d = threadIdx.x & 63, g = threadIdx.x >> 6;
    int s = g_segoff[j], e = g_segoff[j + 1];
    const float* qb = g_q + (size_t)bh * NN * DD;
    const float* kb = g_k + (size_t)bh * NN * DD;
    float sq = 0.f, sk = 0.f;
    for (int i = s + g; i < e; i += 4) {
        sq += qb[(size_t)i * DD + d];
        sk += kb[(size_t)i * DD + d];
    }
    rq[g][d] = sq; rk[g][d] = sk;
    __syncthreads();
    if (g == 0) {
        float tq = rq[0][d] + rq[1][d] + rq[2][d] + rq[3][d];
        float tk = rk[0][d] + rk[1][d] + rk[2][d] + rk[3][d];
        g_ql[((size_t)bh * LL + j) * DD + d] = tq * (1.0f / 64.0f);
        g_kl[((size_t)bh * LL + j) * DD + d] = tk * (1.0f / 64.0f);
    }
}

// ------------------ attn2 = softmax(q_l k_l^T), pitch-68 kl -----------------
__global__ __launch_bounds__(256) void attn2_kernel() {
    __shared__ float skl[LL * 68];
    __shared__ float ss[LL * 66];
    int bh = blockIdx.x, tid = threadIdx.x;
    for (int e = tid; e < LL * DD; e += 256)
        skl[(e >> 6) * 68 + (e & 63)] = g_kl[(size_t)bh * LL * DD + e];
    __syncthreads();
    const float* qb = g_ql + (size_t)bh * LL * DD;
    for (int e = tid; e < LL * LL; e += 256) {
        int i = e / LL, j = e - i * LL;
        float s = 0.f;
        for (int d = 0; d < DD; d += 4) {
            float4 a = *(const float4*)(qb + i * DD + d);
            float4 b = *(float4*)&skl[j * 68 + d];
            s += a.x * b.x + a.y * b.y + a.z * b.z + a.w * b.w;
        }
        ss[i * 66 + j] = s;
    }
    __syncthreads();
    int warp = tid >> 5, lane = tid & 31;
    for (int r = warp; r < LL; r += 8) {
        float mx = -1e30f;
        for (int j = lane; j < LL; j += 32) mx = fmaxf(mx, ss[r * 66 + j]);
        for (int o = 16; o; o >>= 1) mx = fmaxf(mx, __shfl_xor_sync(~0u, mx, o));
        float sum = 0.f;
        for (int j = lane; j < LL; j += 32) {
            float p = expf(ss[r * 66 + j] - mx);
            ss[r * 66 + j] = p; sum += p;
        }
        for (int o = 16; o; o >>= 1) sum += __shfl_xor_sync(~0u, sum, o);
        float inv = 1.f / sum;
        for (int j = lane; j < LL; j += 32)
            g_attn2[((size_t)bh * LL + r) * LL + j] = ss[r * 66 + j] * inv;
    }
}

// ------------------ global scalar ------------------
__global__ __launch_bounds__(256) void scal_kernel() {
    __shared__ float redc[256], redr[256];
    int tid = threadIdx.x;
    float mc = 0.f, mr = 0.f;
    for (int e = tid; e < BHH * LL; e += 256) {
        int bh = e / LL, i = e - bh * LL;
        const float* Xb = g_attn2 + (size_t)bh * LL * LL;
        float rs = 0.f, cs = 0.f;
        for (int j = 0; j < LL; j++) {
            rs += fabsf(Xb[i * LL + j]);
            cs += fabsf(Xb[j * LL + i]);
        }
        mc = fmaxf(mc, rs); mr = fmaxf(mr, cs);
    }
    redc[tid] = mc; redr[tid] = mr;
    __syncthreads();
    for (int s = 128; s > 0; s >>= 1) {
        if (tid < s) {
            redc[tid] = fmaxf(redc[tid], redc[tid + s]);
            redr[tid] = fmaxf(redr[tid], redr[tid + s]);
        }
        __syncthreads();
    }
    if (tid == 0) g_scal[0] = redc[0] * redr[0];
}

// ------------------ Moore-Penrose pinv ------------------
__device__ __forceinline__ void smm65(const float* __restrict__ P,
                                      const float* __restrict__ Q,
                                      float* __restrict__ O,
                                      float beta, float sgn, int tid) {
    for (int t = tid; t < 17 * 17; t += 256) {
        int tr = (t / 17) * 4, tc = (t % 17) * 4;
        float c[4][4] = {};
        for (int k = 0; k < LL; k++) {
            float a[4], b[4];
#pragma unroll
            for (int u = 0; u < 4; u++) { a[u] = P[(tr + u) * 68 + k]; b[u] = Q[k * 68 + tc + u]; }
#pragma unroll
            for (int u = 0; u < 4; u++)
#pragma unroll
                for (int v = 0; v < 4; v++) c[u][v] += a[u] * b[v];
        }
#pragma unroll
        for (int u = 0; u < 4; u++) {
            int i = tr + u; if (i >= LL) continue;
#pragma unroll
            for (int v = 0; v < 4; v++) {
                int j = tc + v; if (j >= LL) continue;
                O[i * 68 + j] = beta * P[i * 68 + j] + sgn * c[u][v];
            }
        }
    }
}

#define PMS (68 * 68)
#define PINV_SMEM (5 * PMS * 4)
__global__ __launch_bounds__(256) void pinv_kernel() {
    extern __shared__ float sm[];
    float* X = sm; float* Z = sm + PMS; float* A_ = sm + 2 * PMS;
    float* Bf = sm + 3 * PMS; float* Cf = sm + 4 * PMS;
    int bh = blockIdx.x, tid = threadIdx.x;
    for (int e = tid; e < 5 * PMS; e += 256) sm[e] = 0.f;
    __syncthreads();
    const float* Xg = g_attn2 + (size_t)bh * LL * LL;
    for (int e = tid; e < LL * LL; e += 256) {
        int i = e / LL, j = e - i * LL;
        X[i * 68 + j] = Xg[e];
    }
    __syncthreads();
    float inva = 1.0f / g_scal[0];
    for (int e = tid; e < LL * LL; e += 256) {
        int i = e / LL, j = e - i * LL;
        Z[i * 68 + j] = X[j * 68 + i] * inva;
    }
    __syncthreads();
    for (int it = 0; it < 6; it++) {
        smm65(X, Z, A_, 0.f, 1.f, tid);  __syncthreads();
        smm65(A_, A_, Bf, 7.f, -1.f, tid); __syncthreads();
        smm65(A_, Bf, Cf, 15.f, -1.f, tid); __syncthreads();
        smm65(Z, Cf, A_, 13.f, -1.f, tid); __syncthreads();
        for (int e = tid; e < LL * LL; e += 256) {
            int i = e / LL, j = e - i * LL;
            Z[i * 68 + j] = 0.25f * A_[i * 68 + j];
        }
        __syncthreads();
    }
    for (int e = tid; e < LL * LL; e += 256) {
        int i = e / LL, j = e - i * LL;
        g_z[(size_t)bh * LL * LL + e] = Z[i * 68 + j];
    }
}

// ------------------ split flash pass (strided rows: conflict-free) ----------
#define SPLIT_SMEM ((LL*68 + 64*68 + 64*DD + LL*DD + LL*66 + 3*LL) * 4)
__global__ __launch_bounds__(256) void split_kernel() {
    extern __shared__ float sm[];
    float* sQ = sm;
    float* sK = sQ + LL * 68;
    float* sV = sK + 64 * 68;
    float* accm = sV + 64 * DD;
    float* sS = accm + LL * DD;
    float* mrow = sS + LL * 66;
    float* lrow = mrow + LL;
    float* frow = lrow + LL;
    int sp = blockIdx.x, bh = blockIdx.y, tid = threadIdx.x;
    const float* Kb = g_k + (size_t)bh * NN * DD;
    const float* Vb = g_v + (size_t)bh * NN * DD;
    const float* Qg = g_ql + (size_t)bh * LL * DD;
    for (int e = tid; e < LL * 16; e += 256) {
        int r = e >> 4, c = (e & 15) << 2;
        *(float4*)&sQ[r * 68 + c] = *(const float4*)(Qg + r * DD + c);
    }
    for (int e = tid; e < LL * DD; e += 256) accm[e] = 0.f;
    if (tid < LL) { mrow[tid] = -1e30f; lrow[tid] = 0.f; }
    __syncthreads();
    int warp = tid >> 5, lane = tid & 31;
    for (int t = 0; t < CHUNK / 64; t++) {
        int i0 = sp * CHUNK + t * 64;
        for (int e = tid; e < 64 * 16; e += 256) {
            int r = e >> 4, c = (e & 15) << 2;
            *(float4*)&sK[r * 68 + c] = *(const float4*)(Kb + (size_t)(i0 + r) * DD + c);
            *(float4*)&sV[r * DD + c] = *(const float4*)(Vb + (size_t)(i0 + r) * DD + c);
        }
        __syncthreads();
        for (int e = tid; e < LL * 16; e += 256) {
            int r = e >> 4, ib = e & 15;
            float s0 = 0.f, s1 = 0.f, s2 = 0.f, s3 = 0.f;
            for (int d = 0; d < DD; d += 4) {
                float4 a = *(float4*)&sQ[r * 68 + d];
                float4 b0 = *(float4*)&sK[(ib + 0)  * 68 + d];
                float4 b1 = *(float4*)&sK[(ib + 16) * 68 + d];
                float4 b2 = *(float4*)&sK[(ib + 32) * 68 + d];
                float4 b3 = *(float4*)&sK[(ib + 48) * 68 + d];
                s0 += a.x * b0.x + a.y * b0.y + a.z * b0.z + a.w * b0.w;
                s1 += a.x * b1.x + a.y * b1.y + a.z * b1.z + a.w * b1.w;
                s2 += a.x * b2.x + a.y * b2.y + a.z * b2.z + a.w * b2.w;
                s3 += a.x * b3.x + a.y * b3.y + a.z * b3.z + a.w * b3.w;
            }
            sS[r * 66 + ib + 0]  = s0;
            sS[r * 66 + ib + 16] = s1;
            sS[r * 66 + ib + 32] = s2;
            sS[r * 66 + ib + 48] = s3;
        }
        __syncthreads();
        for (int r = warp; r < LL; r += 8) {
            float mx = -1e30f;
            for (int i = lane; i < 64; i += 32) mx = fmaxf(mx, sS[r * 66 + i]);
            for (int o = 16; o; o >>= 1) mx = fmaxf(mx, __shfl_xor_sync(~0u, mx, o));
            float mnew = fmaxf(mrow[r], mx);
            float sum = 0.f;
            for (int i = lane; i < 64; i += 32) {
                float p = expf(sS[r * 66 + i] - mnew);
                sS[r * 66 + i] = p; sum += p;
            }
            for (int o = 16; o; o >>= 1) sum += __shfl_xor_sync(~0u, sum, o);
            if (lane == 0) {
                float f = expf(mrow[r] - mnew);
                frow[r] = f;
                lrow[r] = lrow[r] * f + sum;
                mrow[r] = mnew;
            }
        }
        __syncthreads();
        {
            int r = tid >> 4, c = (tid & 15) << 2;
            int r2 = r + 32, r3 = r + 16, r4 = r + 48;
            float f1 = frow[r], f2 = frow[r2], f3 = frow[r3], f4 = frow[r4];
            float4 a1 = *(float4*)&accm[r * DD + c];
            float4 a2 = *(float4*)&accm[r2 * DD + c];
            float4 a3 = *(float4*)&accm[r3 * DD + c];
            float4 a4 = *(float4*)&accm[r4 * DD + c];
            a1.x *= f1; a1.y *= f1; a1.z *= f1; a1.w *= f1;
            a2.x *= f2; a2.y *= f2; a2.z *= f2; a2.w *= f2;
            a3.x *= f3; a3.y *= f3; a3.z *= f3; a3.w *= f3;
            a4.x *= f4; a4.y *= f4; a4.z *= f4; a4.w *= f4;
            for (int i = 0; i < 64; i++) {
                float4 vv = *(float4*)&sV[i * DD + c];
                float p1 = sS[r * 66 + i], p2 = sS[r2 * 66 + i];
                float p3 = sS[r3 * 66 + i], p4 = sS[r4 * 66 + i];
                a1.x += p1 * vv.x; a1.y += p1 * vv.y; a1.z += p1 * vv.z; a1.w += p1 * vv.w;
                a2.x += p2 * vv.x; a2.y += p2 * vv.y; a2.z += p2 * vv.z; a2.w += p2 * vv.w;
                a3.x += p3 * vv.x; a3.y += p3 * vv.y; a3.z += p3 * vv.z; a3.w += p3 * vv.w;
                a4.x += p4 * vv.x; a4.y += p4 * vv.y; a4.z += p4 * vv.z; a4.w += p4 * vv.w;
            }
            *(float4*)&accm[r * DD + c] = a1;
            *(float4*)&accm[r2 * DD + c] = a2;
            *(float4*)&accm[r3 * DD + c] = a3;
            *(float4*)&accm[r4 * DD + c] = a4;
        }
        if (tid < 16) {
            int c = tid << 2;
            float f = frow[64];
            float4 a = *(float4*)&accm[64 * DD + c];
            a.x *= f; a.y *= f; a.z *= f; a.w *= f;
            for (int i = 0; i < 64; i++) {
                float p = sS[64 * 66 + i];
                float4 vv = *(float4*)&sV[i * DD + c];
                a.x += p * vv.x; a.y += p * vv.y; a.z += p * vv.z; a.w += p * vv.w;
            }
            *(float4*)&accm[64 * DD + c] = a;
        }
        __syncthreads();
    }
    size_t pb = (size_t)(bh * NSPLIT + sp);
    for (int e = tid; e < LL * DD; e += 256) g_pacc[pb * LL * DD + e] = accm[e];
    if (tid < LL) { g_pm[pb * LL + tid] = mrow[tid]; g_pl[pb * LL + tid] = lrow[tid]; }
}

// ------------------ combine ------------------
__global__ void combine_kernel() {
    int j = blockIdx.x, bh = blockIdx.y, d = threadIdx.x;
    float M = -1e30f;
    for (int s = 0; s < NSPLIT; s++)
        M = fmaxf(M, g_pm[((size_t)(bh * NSPLIT + s)) * LL + j]);
    float lsum = 0.f, a = 0.f;
    for (int s = 0; s < NSPLIT; s++) {
        size_t pb = (size_t)(bh * NSPLIT + s);
        float w = expf(g_pm[pb * LL + j] - M);
        lsum += w * g_pl[pb * LL + j];
        a += w * g_pacc[(pb * LL + j) * DD + d];
    }
    g_tmp1[((size_t)bh * LL + j) * DD + d] = a / lsum;
}

// ------------------ tmp2 = z @ tmp1 ------------------
__global__ __launch_bounds__(256) void tmp2_kernel() {
    __shared__ float sT[LL * DD];
    __shared__ float sZ[LL * 68];
    int bh = blockIdx.x, tid = threadIdx.x;
    for (int e = tid; e < LL * DD; e += 256) sT[e] = g_tmp1[(size_t)bh * LL * DD + e];
    for (int e = tid; e < LL * LL; e += 256) {
        int i = e / LL, j = e - i * LL;
        sZ[i * 68 + j] = g_z[(size_t)bh * LL * LL + e];
    }
    __syncthreads();
    for (int e = tid; e < LL * 16; e += 256) {
        int j = e >> 4, c = (e & 15) << 2;
        float4 acc = make_float4(0.f, 0.f, 0.f, 0.f);
        for (int m = 0; m < LL; m++) {
            float z = sZ[j * 68 + m];
            float4 t = *(float4*)&sT[m * DD + c];
            acc.x += z * t.x; acc.y += z * t.y; acc.z += z * t.z; acc.w += z * t.w;
        }
        *(float4*)(g_tmp2 + (size_t)bh * LL * DD + j * DD + c) = acc;
    }
}

// ------------------ fused final: strided rows, emits bf16 hi/lo -------------
#define FINAL_SMEM ((68*68 + LL*68 + 32*68 + 64*DD + 32*66 + 36 + 32) * 4)
__global__ __launch_bounds__(256) void final_kernel(const float* __restrict__ wres) {
    extern __shared__ float sm[];
    float* sKL = sm;
    float* sT2 = sKL + 68 * 68;
    float* sQ2 = sT2 + LL * 68;
    float* sVs = sQ2 + 32 * 68;
    float* sS  = sVs + 64 * DD;
    float* sw  = sS + 32 * 66;
    float* sinv = sw + 36;
    int it = blockIdx.x, bh = blockIdx.y, tid = threadIdx.x;
    int hd = bh & 7, b = bh >> 3;
    int i0 = it * 32;
    const float* KLg = g_kl + (size_t)bh * LL * DD;
    const float* T2g = g_tmp2 + (size_t)bh * LL * DD;
    for (int e = tid; e < LL * 16; e += 256) {
        int r = e >> 4, c = (e & 15) << 2;
        *(float4*)&sKL[r * 68 + c] = *(const float4*)(KLg + r * DD + c);
        *(float4*)&sT2[r * 68 + c] = *(const float4*)(T2g + r * DD + c);
    }
    for (int e = tid; e < 3 * 68; e += 256) sKL[65 * 68 + e] = 0.f;
    for (int e = tid; e < 32 * 16; e += 256) {
        int r = e >> 4, c = (e & 15) << 2;
        *(float4*)&sQ2[r * 68 + c] =
            *(const float4*)(g_q + ((size_t)bh * NN + i0 + r) * DD + c);
    }
    for (int e = tid; e < 64 * 16; e += 256) {
        int r = e >> 4, c = (e & 15) << 2;
        int gi = i0 - 16 + r;
        float4 vv = make_float4(0.f, 0.f, 0.f, 0.f);
        if (gi >= 0 && gi < NN) vv = *(const float4*)(g_v + ((size_t)bh * NN + gi) * DD + c);
        *(float4*)&sVs[r * DD + c] = vv;
    }
    if (tid < 33) sw[tid] = wres[hd * 33 + tid];
    __syncthreads();
    for (int e = tid; e < 32 * 17; e += 256) {
        int r = e / 17, jb = e - r * 17;
        float s0 = 0.f, s1 = 0.f, s2 = 0.f, s3 = 0.f;
        for (int d = 0; d < DD; d += 4) {
            float4 a = *(float4*)&sQ2[r * 68 + d];
            float4 b0 = *(float4*)&sKL[(jb + 0)  * 68 + d];
            float4 b1 = *(float4*)&sKL[(jb + 17) * 68 + d];
            float4 b2 = *(float4*)&sKL[(jb + 34) * 68 + d];
            float4 b3 = *(float4*)&sKL[(jb + 51) * 68 + d];
            s0 += a.x * b0.x + a.y * b0.y + a.z * b0.z + a.w * b0.w;
            s1 += a.x * b1.x + a.y * b1.y + a.z * b1.z + a.w * b1.w;
            s2 += a.x * b2.x + a.y * b2.y + a.z * b2.z + a.w * b2.w;
            s3 += a.x * b3.x + a.y * b3.y + a.z * b3.z + a.w * b3.w;
        }
        sS[r * 66 + jb + 0]  = s0;
        sS[r * 66 + jb + 17] = s1;
        sS[r * 66 + jb + 34] = s2;
        if (jb + 51 <= 64) sS[r * 66 + jb + 51] = s3;
    }
    __syncthreads();
    int warp = tid >> 5, lane = tid & 31;
    for (int r = warp; r < 32; r += 8) {
        float mx = -1e30f;
        for (int j = lane; j < LL; j += 32) mx = fmaxf(mx, sS[r * 66 + j]);
        for (int o = 16; o; o >>= 1) mx = fmaxf(mx, __shfl_xor_sync(~0u, mx, o));
        float sum = 0.f;
        for (int j = lane; j < LL; j += 32) {
            float p = expf(sS[r * 66 + j] - mx);
            sS[r * 66 + j] = p; sum += p;
        }
        for (int o = 16; o; o >>= 1) sum += __shfl_xor_sync(~0u, sum, o);
        if (lane == 0) sinv[r] = 1.f / sum;
    }
    __syncthreads();
    {
        int r = tid >> 4, c = (tid & 15) << 2;
        int r2 = r + 16;
        float4 a1 = make_float4(0.f, 0.f, 0.f, 0.f);
        float4 a2 = make_float4(0.f, 0.f, 0.f, 0.f);
        for (int j = 0; j < LL; j++) {
            float4 t = *(float4*)&sT2[j * 68 + c];
            float p1 = sS[r * 66 + j], p2 = sS[r2 * 66 + j];
            a1.x += p1 * t.x; a1.y += p1 * t.y; a1.z += p1 * t.z; a1.w += p1 * t.w;
            a2.x += p2 * t.x; a2.y += p2 * t.y; a2.z += p2 * t.z; a2.w += p2 * t.w;
        }
        float i1 = sinv[r], i2 = sinv[r2];
        a1.x *= i1; a1.y *= i1; a1.z *= i1; a1.w *= i1;
        a2.x *= i2; a2.y *= i2; a2.z *= i2; a2.w *= i2;
        for (int k = 0; k < 33; k++) {
            float wv = sw[k];
            float4 v1 = *(float4*)&sVs[(r + k) * DD + c];
            float4 v2 = *(float4*)&sVs[(r2 + k) * DD + c];
            a1.x += wv * v1.x; a1.y += wv * v1.y; a1.z += wv * v1.z; a1.w += wv * v1.w;
            a2.x += wv * v2.x; a2.y += wv * v2.y; a2.z += wv * v2.z; a2.w += wv * v2.w;
        }
        __nv_bfloat16 h0, h1, h2, h3, l0, l1, l2, l3;
        size_t off1 = ((size_t)b * NN + i0 + r) * DIMM + hd * DD + c;
        size_t off2 = ((size_t)b * NN + i0 + r2) * DIMM + hd * DD + c;
        bf_split(a1.x, h0, l0); bf_split(a1.y, h1, l1);
        bf_split(a1.z, h2, l2); bf_split(a1.w, h3, l3);
        *(uint2*)(g_oh + off1) = make_uint2(pack2(h0, h1), pack2(h2, h3));
        *(uint2*)(g_ol + off1) = make_uint2(pack2(l0, l1), pack2(l2, l3));
        bf_split(a2.x, h0, l0); bf_split(a2.y, h1, l1);
        bf_split(a2.z, h2, l2); bf_split(a2.w, h3, l3);
        *(uint2*)(g_oh + off2) = make_uint2(pack2(h0, h1), pack2(h2, h3));
        *(uint2*)(g_ol + off2) = make_uint2(pack2(l0, l1), pack2(l2, l3));
    }
}

// ------------------ launch ------------------
extern "C" void kernel_launch(void* const* d_in, const int* in_sizes, int n_in,
                              void* d_out, int out_size) {
    const float* x     = (const float*)d_in[0];
    const int*   index = (const int*)d_in[1];
    const int*   seg   = (const int*)d_in[3];
    const float* wqkv  = (const float*)d_in[4];
    const float* wout  = (const float*)d_in[5];
    const float* bout  = (const float*)d_in[6];
    const float* wres  = (const float*)d_in[7];
    float* out = (float*)d_out;

    __nv_bfloat16 *p_wqh, *p_wql, *p_woh, *p_wol;
    cudaGetSymbolAddress((void**)&p_wqh, g_wqh);
    cudaGetSymbolAddress((void**)&p_wql, g_wql);
    cudaGetSymbolAddress((void**)&p_woh, g_woh);
    cudaGetSymbolAddress((void**)&p_wol, g_wol);

    cudaFuncSetAttribute(pinv_kernel,  cudaFuncAttributeMaxDynamicSharedMemorySize, PINV_SMEM);
    cudaFuncSetAttribute(split_kernel, cudaFuncAttributeMaxDynamicSharedMemorySize, SPLIT_SMEM);
    cudaFuncSetAttribute(final_kernel, cudaFuncAttributeMaxDynamicSharedMemorySize, FINAL_SMEM);
    cudaFuncSetAttribute(qkv_mma_kernel, cudaFuncAttributeMaxDynamicSharedMemorySize, GEMM_SMEM);
    cudaFuncSetAttribute(out_mma_kernel, cudaFuncAttributeMaxDynamicSharedMemorySize, GEMM_SMEM);

    seg_init_kernel<<<1, 128>>>();
    seg_count_kernel<<<64, 256>>>(seg);
    seg_scan_kernel<<<1, 32>>>();
    conv_x_kernel<<<8192, 256>>>(x, index);
    conv_w_kernel<<<384, 256>>>(wqkv, p_wqh, p_wql);
    conv_w_kernel<<<128, 256>>>(wout, p_woh, p_wol);
    qkv_mma_kernel<<<dim3(12, 256), 256, GEMM_SMEM>>>();
    landmarks_kernel<<<dim3(LL, BHH), 256>>>();
    attn2_kernel<<<BHH, 256>>>();
    scal_kernel<<<1, 256>>>();
    pinv_kernel<<<BHH, 256, PINV_SMEM>>>();
    split_kernel<<<dim3(NSPLIT, BHH), 256, SPLIT_SMEM>>>();
    combine_kernel<<<dim3(LL, BHH), 64>>>();
    tmp2_kernel<<<BHH, 256>>>();
    final_kernel<<<dim3(NN / 32, BHH), 256, FINAL_SMEM>>>(wres);
    out_mma_kernel<<<dim3(4, 256), 256, GEMM_SMEM>>>(bout, index, out);
}